// round 9
// baseline (speedup 1.0000x reference)
#include <cuda_runtime.h>
#include <cuda_bf16.h>
#include <math_constants.h>
#include <cstdint>

#define BB 2
#define NN 512
#define HH 128
#define DD 128
#define TT 8
#define ZZ 256

#define NTH 512
#define TJ 16             // receivers per tile
#define CI 8              // senders per chunk
#define ISPAN 64          // senders per block
#define IGRP (NN/ISPAN)   // 8 sender groups
#define NCHUNK (ISPAN/CI) // 8 chunks

#define ALD 136           // lead dim (bf16 elems)
// ---- smem offsets (bytes) ----
#define OFF_BH   0
#define OFF_BL   34816
#define OFF_AH   69632
#define OFF_AL   104448
#define OFF_BTH  139264
#define OFF_BTL  141440
#define OFF_STG  143616     // fp32 staging 64KB; reused as reduction scratch at end
#define SMEM_MAIN 209152

// ---------------- scratch ----------------
__device__ float g_M1c[BB*NN*DD];
__device__ float g_M2 [BB*NN*DD];
__device__ float g_T1c[BB*NN*TT];
__device__ float g_T2 [BB*NN*TT];
__device__ float g_o1 [BB*NN*DD];
__device__ float g_gm [BB*DD];
__device__ float g_tg [BB*TT];
__device__ float g_part[IGRP*BB*NN*DD];

__device__ __forceinline__ uint32_t smem_u32(const void* p) {
    uint32_t a;
    asm("{ .reg .u64 t; cvta.to.shared.u64 t, %1; cvt.u32.u64 %0, t; }" : "=r"(a) : "l"(p));
    return a;
}
__device__ __forceinline__ void cvt_hilo(float x, float y, unsigned &hi, unsigned &lo) {
    unsigned bx = __float_as_uint(x) & 0xFFFF0000u;
    unsigned by = __float_as_uint(y) & 0xFFFF0000u;
    hi = __byte_perm(bx, by, 0x7632);
    float lx = x - __uint_as_float(bx);
    float ly = y - __uint_as_float(by);
    asm("cvt.rn.bf16x2.f32 %0, %1, %2;" : "=r"(lo) : "f"(ly), "f"(lx));
}
__device__ __forceinline__ void mma16816(float* c, const uint32_t* a, uint32_t b0, uint32_t b1) {
    asm volatile(
        "mma.sync.aligned.m16n8k16.row.col.f32.bf16.bf16.f32 "
        "{%0,%1,%2,%3}, {%4,%5,%6,%7}, {%8,%9}, {%0,%1,%2,%3};"
        : "+f"(c[0]), "+f"(c[1]), "+f"(c[2]), "+f"(c[3])
        : "r"(a[0]), "r"(a[1]), "r"(a[2]), "r"(a[3]), "r"(b0), "r"(b1));
}
#define LDMX4(r0,r1,r2,r3,addr) \
    asm volatile("ldmatrix.sync.aligned.m8n8.x4.shared.b16 {%0,%1,%2,%3}, [%4];" \
        : "=r"(r0),"=r"(r1),"=r"(r2),"=r"(r3) : "r"(addr))
#define LDMX2(r0,r1,addr) \
    asm volatile("ldmatrix.sync.aligned.m8n8.x2.shared.b16 {%0,%1}, [%2];" \
        : "=r"(r0),"=r"(r1) : "r"(addr))
#define CP_ASYNC16(dst, src) \
    asm volatile("cp.async.cg.shared.global [%0], [%1], 16;" :: "r"(dst), "l"(src) : "memory")
#define CP_COMMIT() asm volatile("cp.async.commit_group;" ::: "memory")
#define CP_WAIT0()  asm volatile("cp.async.wait_group 0;" ::: "memory")

// -------- graph-level terms --------
__global__ void k_graph(const float* __restrict__ graph_fts,
                        const float* __restrict__ Wmg, const float* __restrict__ bmg,
                        const float* __restrict__ Wtg, const float* __restrict__ btg) {
    __shared__ float gs[HH];
    int b = blockIdx.x, t = threadIdx.x;
    gs[t] = graph_fts[b*HH + t];
    __syncthreads();
    float acc = bmg[t];
    #pragma unroll 4
    for (int k = 0; k < HH; k++) acc += gs[k] * Wmg[k*DD + t];
    g_gm[b*DD + t] = acc;
    if (t < TT) {
        float a = btg[t];
        #pragma unroll 4
        for (int k = 0; k < HH; k++) a += gs[k] * Wtg[k*TT + t];
        g_tg[b*TT + t] = a;
    }
}

// -------- per-node precompute: 8 rows per block --------
__global__ void k_node(const float* __restrict__ node, const float* __restrict__ hidden,
                       const float* __restrict__ Wm1, const float* __restrict__ bm1,
                       const float* __restrict__ Wm2, const float* __restrict__ bm2,
                       const float* __restrict__ bme,
                       const float* __restrict__ Wo1, const float* __restrict__ bo1,
                       const float* __restrict__ Wt1, const float* __restrict__ bt1,
                       const float* __restrict__ Wt2, const float* __restrict__ bt2,
                       const float* __restrict__ bte) {
    __shared__ float zs[8][ZZ];
    const int row0 = blockIdx.x * 8;
    const int b    = row0 / NN;
    const int t    = threadIdx.x;   // 128
    #pragma unroll
    for (int r = 0; r < 8; r++) {
        zs[r][t]      = node[(row0 + r)*HH + t];
        zs[r][HH + t] = hidden[(row0 + r)*HH + t];
    }
    __syncthreads();
    float a1[8], a2[8], a3[8];
    const float bia = bm1[t] + bm2[t] + bme[t] + g_gm[b*DD + t];
    const float bio = bo1[t];
    #pragma unroll
    for (int r = 0; r < 8; r++) { a1[r] = bia; a2[r] = 0.f; a3[r] = bio; }
    for (int k = 0; k < ZZ; k++) {
        float w1 = Wm1[k*DD + t], w2 = Wm2[k*DD + t], w3 = Wo1[k*DD + t];
        #pragma unroll
        for (int r = 0; r < 8; r++) {
            float zk = zs[r][k];
            a1[r] += zk*w1; a2[r] += zk*w2; a3[r] += zk*w3;
        }
    }
    #pragma unroll
    for (int r = 0; r < 8; r++) {
        g_M1c[(row0 + r)*DD + t] = a1[r];
        g_M2 [(row0 + r)*DD + t] = a2[r];
        g_o1 [(row0 + r)*DD + t] = a3[r];
    }
    {
        int r = t >> 4, which = (t >> 3) & 1, tt = t & 7;
        const float* W = which ? Wt2 : Wt1;
        float a = which ? 0.f : (bt1[tt] + bt2[tt] + bte[tt] + g_tg[b*TT + tt]);
        #pragma unroll 4
        for (int k = 0; k < ZZ; k++) a += zs[r][k] * W[k*TT + tt];
        if (which) g_T2 [(row0 + r)*TT + tt] = a;
        else       g_T1c[(row0 + r)*TT + tt] = a;
    }
}

// -------- fused edge GEMM (mma.sync bf16 hi/lo) + register epilogue --------
__global__ void __launch_bounds__(NTH, 1)
k_main(const float* __restrict__ edge, const float* __restrict__ adj,
       const float* __restrict__ Wme, const float* __restrict__ Wte,
       float* __restrict__ tri_out) {
    extern __shared__ char sm[];
    const uint32_t smb = smem_u32(sm);
    const int tid  = threadIdx.x;
    const int lane = tid & 31, wid = tid >> 5;
    const int qr   = lane >> 2, qc = lane & 3;
    const int wm   = wid >> 2, wn = wid & 3;     // 4m x 4n warp grid
    const int jb   = blockIdx.x, ig = blockIdx.y, b = blockIdx.z;
    const int j0   = jb * TJ;
    const int i0   = ig * ISPAN;

    // ---- prefetch chunk 0
    {
        const size_t base = ((size_t)b*NN)*NN*HH;
        #pragma unroll
        for (int q = 0; q < 8; q++) {
            int F4 = q*NTH + tid;
            int e  = F4 >> 5, k = (F4 & 31) << 2;
            int di = e >> 4, dj = e & 15;
            const float* src = edge + base + ((size_t)(i0 + di)*NN + (j0 + dj))*(size_t)HH + k;
            CP_ASYNC16(smb + OFF_STG + F4*16, src);
        }
        CP_COMMIT();
    }

    // ---- convert B = Wme -> [n][k] bf16 hi/lo
    for (int idx = tid; idx < HH*DD; idx += NTH) {
        int k = idx >> 7, n = idx & 127;
        float w = Wme[idx];
        unsigned bw = __float_as_uint(w) & 0xFFFF0000u;
        *(unsigned short*)(sm + OFF_BH + (n*ALD + k)*2) = (unsigned short)(bw >> 16);
        *(__nv_bfloat16*)(sm + OFF_BL + (n*ALD + k)*2) = __float2bfloat16(w - __uint_as_float(bw));
    }
    for (int idx = tid; idx < HH*TT; idx += NTH) {
        int k = idx >> 3, n = idx & 7;
        float w = Wte[idx];
        unsigned bw = __float_as_uint(w) & 0xFFFF0000u;
        *(unsigned short*)(sm + OFF_BTH + (n*ALD + k)*2) = (unsigned short)(bw >> 16);
        *(__nv_bfloat16*)(sm + OFF_BTL + (n*ALD + k)*2) = __float2bfloat16(w - __uint_as_float(bw));
    }

    // fragment base offsets (ldmatrix lane addressing; identical to prior passing rounds)
    const uint32_t aoff  = (uint32_t)(((wm*32 + (lane & 15))*ALD + ((lane >> 4) << 3)) * 2);
    const uint32_t boff  = (uint32_t)(((wn*32 + ((lane >> 4) << 3) + (lane & 7))*ALD + (((lane >> 3) & 1) << 3)) * 2);
    const uint32_t btoff = (uint32_t)(((lane & 7)*ALD + (((lane >> 3) & 1) << 3)) * 2);
    const uint32_t aHb = smb + OFF_AH + aoff,  aLb = smb + OFF_AL + aoff;
    const uint32_t bHb = smb + OFF_BH + boff,  bLb = smb + OFF_BL + boff;
    const uint32_t tHb = smb + OFF_BTH + btoff, tLb = smb + OFF_BTL + btoff;

    // persistent per-thread masked-max state
    // rmax[nt][q]: q0,1 -> receiver j0+qr, cols wn*32+nt*8+2qc+{0,1}; q2,3 -> receiver j0+qr+8
    float rmax[4][4];
    #pragma unroll
    for (int nt = 0; nt < 4; nt++)
        #pragma unroll
        for (int q = 0; q < 4; q++) rmax[nt][q] = -CUDART_INF_F;
    bool sawz0 = false, sawz1 = false;

    for (int ci = 0; ci < NCHUNK; ci++) {
        const int i0c = i0 + ci*CI;
        CP_WAIT0();
        __syncthreads();   // staging ready; prev chunk's A-frag reads done

        // ---- convert staging fp32 -> A hi/lo
        {
            const float4* stg = (const float4*)(sm + OFF_STG);
            #pragma unroll
            for (int q = 0; q < 8; q++) {
                int F4 = q*NTH + tid;
                float4 v = stg[F4];
                int e = F4 >> 5, k = (F4 & 31) << 2;
                unsigned h01, l01, h23, l23;
                cvt_hilo(v.x, v.y, h01, l01);
                cvt_hilo(v.z, v.w, h23, l23);
                *(uint2*)(sm + OFF_AH + (e*ALD + k)*2) = make_uint2(h01, h23);
                *(uint2*)(sm + OFF_AL + (e*ALD + k)*2) = make_uint2(l01, l23);
            }
        }
        __syncthreads();   // A ready; staging reads done -> safe to prefetch

        if (ci + 1 < NCHUNK) {
            const size_t base = ((size_t)b*NN)*NN*HH;
            const int i0n = i0c + CI;
            #pragma unroll
            for (int q = 0; q < 8; q++) {
                int F4 = q*NTH + tid;
                int e  = F4 >> 5, k = (F4 & 31) << 2;
                int di = e >> 4, dj = e & 15;
                const float* src = edge + base + ((size_t)(i0n + di)*NN + (j0 + dj))*(size_t)HH + k;
                CP_ASYNC16(smb + OFF_STG + F4*16, src);
            }
            CP_COMMIT();
        }

        // ---- MMA: fused 3 products
        float c[2][4][4];
        float ct[4] = {0.f, 0.f, 0.f, 0.f};
        #pragma unroll
        for (int mt = 0; mt < 2; mt++)
            #pragma unroll
            for (int nt = 0; nt < 4; nt++)
                #pragma unroll
                for (int q = 0; q < 4; q++) c[mt][nt][q] = 0.f;

        #pragma unroll
        for (int ks = 0; ks < 8; ks++) {
            const uint32_t kb = ks * 32;
            uint32_t aH[2][4], aL[2][4], bH[2][4], bL[2][4];
            LDMX4(aH[0][0], aH[0][1], aH[0][2], aH[0][3], aHb + kb);
            LDMX4(aH[1][0], aH[1][1], aH[1][2], aH[1][3], aHb + 16*ALD*2 + kb);
            LDMX4(aL[0][0], aL[0][1], aL[0][2], aL[0][3], aLb + kb);
            LDMX4(aL[1][0], aL[1][1], aL[1][2], aL[1][3], aLb + 16*ALD*2 + kb);
            LDMX4(bH[0][0], bH[0][1], bH[0][2], bH[0][3], bHb + kb);
            LDMX4(bH[1][0], bH[1][1], bH[1][2], bH[1][3], bHb + 16*ALD*2 + kb);
            LDMX4(bL[0][0], bL[0][1], bL[0][2], bL[0][3], bLb + kb);
            LDMX4(bL[1][0], bL[1][1], bL[1][2], bL[1][3], bLb + 16*ALD*2 + kb);
            #pragma unroll
            for (int nt = 0; nt < 4; nt++) {
                uint32_t b0h = bH[nt>>1][(nt&1)*2], b1h = bH[nt>>1][(nt&1)*2+1];
                uint32_t b0l = bL[nt>>1][(nt&1)*2], b1l = bL[nt>>1][(nt&1)*2+1];
                #pragma unroll
                for (int mt = 0; mt < 2; mt++) {
                    mma16816(c[mt][nt], aH[mt], b0h, b1h);
                    mma16816(c[mt][nt], aH[mt], b0l, b1l);
                    mma16816(c[mt][nt], aL[mt], b0h, b1h);
                }
            }
            if (wn < 2) {   // tri tile for sender index wm*2 + wn
                uint32_t t0h, t1h, t0l, t1l;
                LDMX2(t0h, t1h, tHb + kb);
                LDMX2(t0l, t1l, tLb + kb);
                const uint32_t* ah = wn ? aH[1] : aH[0];
                const uint32_t* al = wn ? aL[1] : aL[0];
                mma16816(ct, ah, t0h, t1h);
                mma16816(ct, ah, t0l, t1l);
                mma16816(ct, al, t0h, t1h);
            }
        }

        // ---- register epilogue: tri write (wn<2)
        if (wn < 2) {
            const int i  = i0c + wm*2 + wn;
            const float2 t2v = *(const float2*)(&g_T2[((size_t)b*NN + i)*TT + 2*qc]);
            const int ja = j0 + qr, jb2 = j0 + qr + 8;
            float2 t1a = *(const float2*)(&g_T1c[((size_t)b*NN + ja )*TT + 2*qc]);
            float2 t1b = *(const float2*)(&g_T1c[((size_t)b*NN + jb2)*TT + 2*qc]);
            float2 oa, ob;
            oa.x = fmaxf(ct[0] + t1a.x + t2v.x, 0.f);
            oa.y = fmaxf(ct[1] + t1a.y + t2v.y, 0.f);
            ob.x = fmaxf(ct[2] + t1b.x + t2v.x, 0.f);
            ob.y = fmaxf(ct[3] + t1b.y + t2v.y, 0.f);
            *(float2*)(tri_out + (((size_t)b*NN + i)*NN + ja )*(size_t)TT + 2*qc) = oa;
            *(float2*)(tri_out + (((size_t)b*NN + i)*NN + jb2)*(size_t)TT + 2*qc) = ob;
        }
        // ---- register epilogue: masked max (each m16 tile = one sender x 16 receivers)
        #pragma unroll
        for (int mt = 0; mt < 2; mt++) {
            const int i = i0c + wm*2 + mt;
            const float a0 = adj[((size_t)b*NN + i)*NN + j0 + qr];
            const float a1 = adj[((size_t)b*NN + i)*NN + j0 + qr + 8];
            float2 m2v[4];
            #pragma unroll
            for (int nt = 0; nt < 4; nt++)
                m2v[nt] = *(const float2*)(&g_M2[((size_t)b*NN + i)*DD + wn*32 + nt*8 + 2*qc]);
            if (a0 != 0.0f) {
                #pragma unroll
                for (int nt = 0; nt < 4; nt++) {
                    rmax[nt][0] = fmaxf(rmax[nt][0], c[mt][nt][0] + m2v[nt].x);
                    rmax[nt][1] = fmaxf(rmax[nt][1], c[mt][nt][1] + m2v[nt].y);
                }
            } else sawz0 = true;
            if (a1 != 0.0f) {
                #pragma unroll
                for (int nt = 0; nt < 4; nt++) {
                    rmax[nt][2] = fmaxf(rmax[nt][2], c[mt][nt][2] + m2v[nt].x);
                    rmax[nt][3] = fmaxf(rmax[nt][3], c[mt][nt][3] + m2v[nt].y);
                }
            } else sawz1 = true;
        }
    }

    // ---- cross-wm combine in (now free) staging smem
    float* red  = (float*)(sm + OFF_STG);          // [2][16][128]
    float* zbuf = (float*)(sm + OFF_STG + 2*16*128*4); // [4][16]
    __syncthreads();
    if (wn == 0 && qc == 0) {
        zbuf[wm*16 + qr]     = sawz0 ? 0.0f : -CUDART_INF_F;
        zbuf[wm*16 + qr + 8] = sawz1 ? 0.0f : -CUDART_INF_F;
    }
    if (wm >= 2) {
        #pragma unroll
        for (int nt = 0; nt < 4; nt++) {
            #pragma unroll
            for (int q = 0; q < 4; q++) {
                int recv = qr + (q >> 1)*8;
                int col  = wn*32 + nt*8 + 2*qc + (q & 1);
                red[(((wm-2)*16) + recv)*128 + col] = rmax[nt][q];
            }
        }
    }
    __syncthreads();
    if (wm < 2) {
        #pragma unroll
        for (int nt = 0; nt < 4; nt++) {
            #pragma unroll
            for (int q = 0; q < 4; q++) {
                int recv = qr + (q >> 1)*8;
                int col  = wn*32 + nt*8 + 2*qc + (q & 1);
                rmax[nt][q] = fmaxf(rmax[nt][q], red[(wm*16 + recv)*128 + col]);
            }
        }
    }
    __syncthreads();
    if (wm == 1) {
        #pragma unroll
        for (int nt = 0; nt < 4; nt++) {
            #pragma unroll
            for (int q = 0; q < 4; q++) {
                int recv = qr + (q >> 1)*8;
                int col  = wn*32 + nt*8 + 2*qc + (q & 1);
                red[recv*128 + col] = rmax[nt][q];
            }
        }
    }
    __syncthreads();
    if (wm == 0) {
        #pragma unroll
        for (int q2 = 0; q2 < 2; q2++) {   // receiver half
            const int recv = qr + q2*8;
            const int j = j0 + recv;
            const float z = fmaxf(fmaxf(zbuf[recv], zbuf[16 + recv]),
                                  fmaxf(zbuf[32 + recv], zbuf[48 + recv]));
            #pragma unroll
            for (int nt = 0; nt < 4; nt++) {
                const int col = wn*32 + nt*8 + 2*qc;
                float v0 = fmaxf(rmax[nt][q2*2 + 0], red[recv*128 + col]);
                float v1 = fmaxf(rmax[nt][q2*2 + 1], red[recv*128 + col + 1]);
                float2 m1 = *(const float2*)(&g_M1c[((size_t)b*NN + j)*DD + col]);
                float2 o;
                o.x = fmaxf(v0 + m1.x, z);
                o.y = fmaxf(v1 + m1.y, z);
                *(float2*)(&g_part[(((size_t)ig*BB + b)*NN + j)*DD + col]) = o;
            }
        }
    }
}

// -------- output head: reduce partials + Wo2 GEMM, 4 rows per block --------
__global__ void k_final(const float* __restrict__ Wo2, const float* __restrict__ bo2,
                        float* __restrict__ ret) {
    __shared__ float ms[4][DD];
    const int row0 = blockIdx.x * 4;
    const int t = threadIdx.x;      // 128
    #pragma unroll
    for (int r = 0; r < 4; r++) {
        float v = -CUDART_INF_F;
        #pragma unroll
        for (int g = 0; g < IGRP; g++)
            v = fmaxf(v, g_part[(size_t)g*BB*NN*DD + (size_t)(row0 + r)*DD + t]);
        ms[r][t] = v;
    }
    __syncthreads();
    float acc[4];
    const float bia = bo2[t];
    #pragma unroll
    for (int r = 0; r < 4; r++) acc[r] = g_o1[(row0 + r)*DD + t] + bia;
    for (int k = 0; k < DD; k++) {
        float w = Wo2[k*DD + t];
        #pragma unroll
        for (int r = 0; r < 4; r++) acc[r] += ms[r][k] * w;
    }
    #pragma unroll
    for (int r = 0; r < 4; r++) ret[(row0 + r)*DD + t] = acc[r];
}

extern "C" void kernel_launch(void* const* d_in, const int* in_sizes, int n_in,
                              void* d_out, int out_size) {
    (void)in_sizes; (void)n_in; (void)out_size;
    const float* node   = (const float*)d_in[0];
    const float* edge   = (const float*)d_in[1];
    const float* graph  = (const float*)d_in[2];
    const float* adj    = (const float*)d_in[3];
    const float* hidden = (const float*)d_in[4];
    const float* Wm1 = (const float*)d_in[5],  *bm1 = (const float*)d_in[6];
    const float* Wm2 = (const float*)d_in[7],  *bm2 = (const float*)d_in[8];
    const float* Wme = (const float*)d_in[9],  *bme = (const float*)d_in[10];
    const float* Wmg = (const float*)d_in[11], *bmg = (const float*)d_in[12];
    const float* Wo1 = (const float*)d_in[13], *bo1 = (const float*)d_in[14];
    const float* Wo2 = (const float*)d_in[15], *bo2 = (const float*)d_in[16];
    const float* Wt1 = (const float*)d_in[17], *bt1 = (const float*)d_in[18];
    const float* Wt2 = (const float*)d_in[19], *bt2 = (const float*)d_in[20];
    const float* Wte = (const float*)d_in[21], *bte = (const float*)d_in[22];
    const float* Wtg = (const float*)d_in[23], *btg = (const float*)d_in[24];

    float* ret = (float*)d_out;
    float* tri = (float*)d_out + (size_t)BB*NN*DD;

    cudaFuncSetAttribute(k_main, cudaFuncAttributeMaxDynamicSharedMemorySize, SMEM_MAIN);

    k_graph<<<BB, 128>>>(graph, Wmg, bmg, Wtg, btg);
    k_node<<<BB*NN/8, 128>>>(node, hidden, Wm1, bm1, Wm2, bm2, bme,
                             Wo1, bo1, Wt1, bt1, Wt2, bt2, bte);
    k_main<<<dim3(NN/TJ, IGRP, BB), NTH, SMEM_MAIN>>>(edge, adj, Wme, Wte, tri);
    k_final<<<BB*NN/4, 128>>>(Wo2, bo2, ret);
}

// round 10
// speedup vs baseline: 1.3081x; 1.3081x over previous
#include <cuda_runtime.h>
#include <cuda_bf16.h>
#include <math_constants.h>
#include <cstdint>

#define BB 2
#define NN 512
#define HH 128
#define DD 128
#define TT 8
#define ZZ 256

#define NTH 256
#define TJ 16             // receivers per tile
#define CI 8              // senders per chunk
#define ISPAN 64          // senders per block
#define IGRP (NN/ISPAN)   // 8 sender groups
#define NCHUNK (ISPAN/CI) // 8 chunks

#define ALD 136           // lead dim (bf16 elems)
// ---- smem offsets (bytes) ----
#define OFF_BH   0
#define OFF_BL   34816
#define OFF_AH   69632
#define OFF_AL   104448
#define OFF_BTH  139264
#define OFF_BTL  141440
#define OFF_STG  143616     // fp32 staging 64KB; reused as reduction scratch at end
#define SMEM_MAIN 209152

// ---------------- scratch ----------------
__device__ float g_M1c[BB*NN*DD];
__device__ float g_M2 [BB*NN*DD];
__device__ float g_T1c[BB*NN*TT];
__device__ float g_T2 [BB*NN*TT];
__device__ float g_o1 [BB*NN*DD];
__device__ float g_gm [BB*DD];
__device__ float g_tg [BB*TT];
__device__ float g_part[IGRP*BB*NN*DD];

__device__ __forceinline__ uint32_t smem_u32(const void* p) {
    uint32_t a;
    asm("{ .reg .u64 t; cvta.to.shared.u64 t, %1; cvt.u32.u64 %0, t; }" : "=r"(a) : "l"(p));
    return a;
}
__device__ __forceinline__ void cvt_hilo(float x, float y, unsigned &hi, unsigned &lo) {
    unsigned bx = __float_as_uint(x) & 0xFFFF0000u;
    unsigned by = __float_as_uint(y) & 0xFFFF0000u;
    hi = __byte_perm(bx, by, 0x7632);
    float lx = x - __uint_as_float(bx);
    float ly = y - __uint_as_float(by);
    asm("cvt.rn.bf16x2.f32 %0, %1, %2;" : "=r"(lo) : "f"(ly), "f"(lx));
}
__device__ __forceinline__ void mma16816(float* c, const uint32_t* a, uint32_t b0, uint32_t b1) {
    asm volatile(
        "mma.sync.aligned.m16n8k16.row.col.f32.bf16.bf16.f32 "
        "{%0,%1,%2,%3}, {%4,%5,%6,%7}, {%8,%9}, {%0,%1,%2,%3};"
        : "+f"(c[0]), "+f"(c[1]), "+f"(c[2]), "+f"(c[3])
        : "r"(a[0]), "r"(a[1]), "r"(a[2]), "r"(a[3]), "r"(b0), "r"(b1));
}
#define LDMX4(r0,r1,r2,r3,addr) \
    asm volatile("ldmatrix.sync.aligned.m8n8.x4.shared.b16 {%0,%1,%2,%3}, [%4];" \
        : "=r"(r0),"=r"(r1),"=r"(r2),"=r"(r3) : "r"(addr))
#define LDMX2(r0,r1,addr) \
    asm volatile("ldmatrix.sync.aligned.m8n8.x2.shared.b16 {%0,%1}, [%2];" \
        : "=r"(r0),"=r"(r1) : "r"(addr))
#define CP_ASYNC16(dst, src) \
    asm volatile("cp.async.cg.shared.global [%0], [%1], 16;" :: "r"(dst), "l"(src) : "memory")
#define CP_COMMIT() asm volatile("cp.async.commit_group;" ::: "memory")
#define CP_WAIT0()  asm volatile("cp.async.wait_group 0;" ::: "memory")

// -------- graph-level terms --------
__global__ void k_graph(const float* __restrict__ graph_fts,
                        const float* __restrict__ Wmg, const float* __restrict__ bmg,
                        const float* __restrict__ Wtg, const float* __restrict__ btg) {
    __shared__ float gs[HH];
    int b = blockIdx.x, t = threadIdx.x;
    gs[t] = graph_fts[b*HH + t];
    __syncthreads();
    float acc = bmg[t];
    #pragma unroll 4
    for (int k = 0; k < HH; k++) acc += gs[k] * Wmg[k*DD + t];
    g_gm[b*DD + t] = acc;
    if (t < TT) {
        float a = btg[t];
        #pragma unroll 4
        for (int k = 0; k < HH; k++) a += gs[k] * Wtg[k*TT + t];
        g_tg[b*TT + t] = a;
    }
}

// -------- per-node precompute: 8 rows per block --------
__global__ void k_node(const float* __restrict__ node, const float* __restrict__ hidden,
                       const float* __restrict__ Wm1, const float* __restrict__ bm1,
                       const float* __restrict__ Wm2, const float* __restrict__ bm2,
                       const float* __restrict__ bme,
                       const float* __restrict__ Wo1, const float* __restrict__ bo1,
                       const float* __restrict__ Wt1, const float* __restrict__ bt1,
                       const float* __restrict__ Wt2, const float* __restrict__ bt2,
                       const float* __restrict__ bte) {
    __shared__ float zs[8][ZZ];
    const int row0 = blockIdx.x * 8;
    const int b    = row0 / NN;
    const int t    = threadIdx.x;   // 128
    #pragma unroll
    for (int r = 0; r < 8; r++) {
        zs[r][t]      = node[(row0 + r)*HH + t];
        zs[r][HH + t] = hidden[(row0 + r)*HH + t];
    }
    __syncthreads();
    float a1[8], a2[8], a3[8];
    const float bia = bm1[t] + bm2[t] + bme[t] + g_gm[b*DD + t];
    const float bio = bo1[t];
    #pragma unroll
    for (int r = 0; r < 8; r++) { a1[r] = bia; a2[r] = 0.f; a3[r] = bio; }
    for (int k = 0; k < ZZ; k++) {
        float w1 = Wm1[k*DD + t], w2 = Wm2[k*DD + t], w3 = Wo1[k*DD + t];
        #pragma unroll
        for (int r = 0; r < 8; r++) {
            float zk = zs[r][k];
            a1[r] += zk*w1; a2[r] += zk*w2; a3[r] += zk*w3;
        }
    }
    #pragma unroll
    for (int r = 0; r < 8; r++) {
        g_M1c[(row0 + r)*DD + t] = a1[r];
        g_M2 [(row0 + r)*DD + t] = a2[r];
        g_o1 [(row0 + r)*DD + t] = a3[r];
    }
    {
        int r = t >> 4, which = (t >> 3) & 1, tt = t & 7;
        const float* W = which ? Wt2 : Wt1;
        float a = which ? 0.f : (bt1[tt] + bt2[tt] + bte[tt] + g_tg[b*TT + tt]);
        #pragma unroll 4
        for (int k = 0; k < ZZ; k++) a += zs[r][k] * W[k*TT + tt];
        if (which) g_T2 [(row0 + r)*TT + tt] = a;
        else       g_T1c[(row0 + r)*TT + tt] = a;
    }
}

// -------- fused edge GEMM (mma.sync bf16 hi/lo) + register epilogue --------
__global__ void __launch_bounds__(NTH, 1)
k_main(const float* __restrict__ edge, const float* __restrict__ adj,
       const float* __restrict__ Wme, const float* __restrict__ Wte,
       float* __restrict__ tri_out, int ig_base) {
    extern __shared__ char sm[];
    const uint32_t smb = smem_u32(sm);
    const int tid  = threadIdx.x;
    const int lane = tid & 31, wid = tid >> 5;
    const int qr   = lane >> 2, qc = lane & 3;
    const int wm   = wid >> 2, wn = wid & 3;     // 2m x 4n warp grid, m64 x n32 per warp
    const int jb   = blockIdx.x, ig = ig_base + blockIdx.y, b = blockIdx.z;
    const int j0   = jb * TJ;
    const int i0   = ig * ISPAN;

    // ---- prefetch chunk 0 into staging
    {
        const size_t base = ((size_t)b*NN)*NN*HH;
        #pragma unroll
        for (int q = 0; q < 16; q++) {
            int F4 = q*NTH + tid;
            int e  = F4 >> 5, k = (F4 & 31) << 2;
            int di = e >> 4, dj = e & 15;
            const float* src = edge + base + ((size_t)(i0 + di)*NN + (j0 + dj))*(size_t)HH + k;
            CP_ASYNC16(smb + OFF_STG + F4*16, src);
        }
        CP_COMMIT();
    }

    // ---- convert B = Wme -> [n][k] bf16 hi/lo
    for (int idx = tid; idx < HH*DD; idx += NTH) {
        int k = idx >> 7, n = idx & 127;
        float w = Wme[idx];
        unsigned bw = __float_as_uint(w) & 0xFFFF0000u;
        *(unsigned short*)(sm + OFF_BH + (n*ALD + k)*2) = (unsigned short)(bw >> 16);
        *(__nv_bfloat16*)(sm + OFF_BL + (n*ALD + k)*2) = __float2bfloat16(w - __uint_as_float(bw));
    }
    for (int idx = tid; idx < HH*TT; idx += NTH) {
        int k = idx >> 3, n = idx & 7;
        float w = Wte[idx];
        unsigned bw = __float_as_uint(w) & 0xFFFF0000u;
        *(unsigned short*)(sm + OFF_BTH + (n*ALD + k)*2) = (unsigned short)(bw >> 16);
        *(__nv_bfloat16*)(sm + OFF_BTL + (n*ALD + k)*2) = __float2bfloat16(w - __uint_as_float(bw));
    }

    // fragment base offsets (ldmatrix lane addressing; same scheme as passing rounds)
    const uint32_t aoff  = (uint32_t)(((wm*64 + (lane & 15))*ALD + ((lane >> 4) << 3)) * 2);
    const uint32_t boff  = (uint32_t)(((wn*32 + ((lane >> 4) << 3) + (lane & 7))*ALD + (((lane >> 3) & 1) << 3)) * 2);
    const uint32_t btoff = (uint32_t)(((lane & 7)*ALD + (((lane >> 3) & 1) << 3)) * 2);
    const uint32_t aHb = smb + OFF_AH + aoff,  aLb = smb + OFF_AL + aoff;
    const uint32_t bHb = smb + OFF_BH + boff,  bLb = smb + OFF_BL + boff;
    const uint32_t tHb = smb + OFF_BTH + btoff, tLb = smb + OFF_BTL + btoff;

    // persistent per-thread masked-max state
    // rmax[nt][q]: q0,1 -> receiver j0+qr, cols wn*32+nt*8+2qc+{0,1}; q2,3 -> receiver j0+qr+8
    float rmax[4][4];
    #pragma unroll
    for (int nt = 0; nt < 4; nt++)
        #pragma unroll
        for (int q = 0; q < 4; q++) rmax[nt][q] = -CUDART_INF_F;
    bool sawz0 = false, sawz1 = false;

    for (int ci = 0; ci < NCHUNK; ci++) {
        const int i0c = i0 + ci*CI;
        CP_WAIT0();
        __syncthreads();   // staging ready; prev chunk's A-frag reads done

        // ---- convert staging fp32 -> A hi/lo
        {
            const float4* stg = (const float4*)(sm + OFF_STG);
            #pragma unroll
            for (int q = 0; q < 16; q++) {
                int F4 = q*NTH + tid;
                float4 v = stg[F4];
                int e = F4 >> 5, k = (F4 & 31) << 2;
                unsigned h01, l01, h23, l23;
                cvt_hilo(v.x, v.y, h01, l01);
                cvt_hilo(v.z, v.w, h23, l23);
                *(uint2*)(sm + OFF_AH + (e*ALD + k)*2) = make_uint2(h01, h23);
                *(uint2*)(sm + OFF_AL + (e*ALD + k)*2) = make_uint2(l01, l23);
            }
        }
        __syncthreads();   // A ready; staging reads done -> safe to prefetch next

        if (ci + 1 < NCHUNK) {
            const size_t base = ((size_t)b*NN)*NN*HH;
            const int i0n = i0c + CI;
            #pragma unroll
            for (int q = 0; q < 16; q++) {
                int F4 = q*NTH + tid;
                int e  = F4 >> 5, k = (F4 & 31) << 2;
                int di = e >> 4, dj = e & 15;
                const float* src = edge + base + ((size_t)(i0n + di)*NN + (j0 + dj))*(size_t)HH + k;
                CP_ASYNC16(smb + OFF_STG + F4*16, src);
            }
            CP_COMMIT();
        }

        // ---- MMA: fused 3 products, m64 x n32 per warp
        float c[4][4][4];
        float ct[4] = {0.f, 0.f, 0.f, 0.f};
        #pragma unroll
        for (int mt = 0; mt < 4; mt++)
            #pragma unroll
            for (int nt = 0; nt < 4; nt++)
                #pragma unroll
                for (int q = 0; q < 4; q++) c[mt][nt][q] = 0.f;

        #pragma unroll
        for (int ks = 0; ks < 8; ks++) {
            const uint32_t kb = ks * 32;
            uint32_t bH[2][4], bL[2][4];
            LDMX4(bH[0][0], bH[0][1], bH[0][2], bH[0][3], bHb + kb);
            LDMX4(bH[1][0], bH[1][1], bH[1][2], bH[1][3], bHb + 16*ALD*2 + kb);
            LDMX4(bL[0][0], bL[0][1], bL[0][2], bL[0][3], bLb + kb);
            LDMX4(bL[1][0], bL[1][1], bL[1][2], bL[1][3], bLb + 16*ALD*2 + kb);
            uint32_t t0h, t1h, t0l, t1l;
            LDMX2(t0h, t1h, tHb + kb);
            LDMX2(t0l, t1l, tLb + kb);
            #pragma unroll
            for (int mt = 0; mt < 4; mt++) {
                uint32_t aH[4], aL[4];
                LDMX4(aH[0], aH[1], aH[2], aH[3], aHb + mt*16*ALD*2 + kb);
                LDMX4(aL[0], aL[1], aL[2], aL[3], aLb + mt*16*ALD*2 + kb);
                #pragma unroll
                for (int nt = 0; nt < 4; nt++) {
                    uint32_t b0h = bH[nt>>1][(nt&1)*2], b1h = bH[nt>>1][(nt&1)*2+1];
                    uint32_t b0l = bL[nt>>1][(nt&1)*2], b1l = bL[nt>>1][(nt&1)*2+1];
                    mma16816(c[mt][nt], aH, b0h, b1h);
                    mma16816(c[mt][nt], aH, b0l, b1l);
                    mma16816(c[mt][nt], aL, b0h, b1h);
                }
                if (mt == wn) {   // tri tile for sender wm*4 + wn
                    mma16816(ct, aH, t0h, t1h);
                    mma16816(ct, aH, t0l, t1l);
                    mma16816(ct, aL, t0h, t1h);
                }
            }
        }

        // ---- register epilogue: tri write (sender i = i0c + wm*4 + wn)
        {
            const int i  = i0c + wm*4 + wn;
            const float2 t2v = *(const float2*)(&g_T2[((size_t)b*NN + i)*TT + 2*qc]);
            const int ja = j0 + qr, jb2 = j0 + qr + 8;
            float2 t1a = *(const float2*)(&g_T1c[((size_t)b*NN + ja )*TT + 2*qc]);
            float2 t1b = *(const float2*)(&g_T1c[((size_t)b*NN + jb2)*TT + 2*qc]);
            float2 oa, ob;
            oa.x = fmaxf(ct[0] + t1a.x + t2v.x, 0.f);
            oa.y = fmaxf(ct[1] + t1a.y + t2v.y, 0.f);
            ob.x = fmaxf(ct[2] + t1b.x + t2v.x, 0.f);
            ob.y = fmaxf(ct[3] + t1b.y + t2v.y, 0.f);
            *(float2*)(tri_out + (((size_t)b*NN + i)*NN + ja )*(size_t)TT + 2*qc) = oa;
            *(float2*)(tri_out + (((size_t)b*NN + i)*NN + jb2)*(size_t)TT + 2*qc) = ob;
        }
        // ---- register epilogue: masked max (each m16 tile = one sender x 16 receivers)
        #pragma unroll
        for (int mt = 0; mt < 4; mt++) {
            const int i = i0c + wm*4 + mt;
            const float a0 = adj[((size_t)b*NN + i)*NN + j0 + qr];
            const float a1 = adj[((size_t)b*NN + i)*NN + j0 + qr + 8];
            float2 m2v[4];
            #pragma unroll
            for (int nt = 0; nt < 4; nt++)
                m2v[nt] = *(const float2*)(&g_M2[((size_t)b*NN + i)*DD + wn*32 + nt*8 + 2*qc]);
            if (a0 != 0.0f) {
                #pragma unroll
                for (int nt = 0; nt < 4; nt++) {
                    rmax[nt][0] = fmaxf(rmax[nt][0], c[mt][nt][0] + m2v[nt].x);
                    rmax[nt][1] = fmaxf(rmax[nt][1], c[mt][nt][1] + m2v[nt].y);
                }
            } else sawz0 = true;
            if (a1 != 0.0f) {
                #pragma unroll
                for (int nt = 0; nt < 4; nt++) {
                    rmax[nt][2] = fmaxf(rmax[nt][2], c[mt][nt][2] + m2v[nt].x);
                    rmax[nt][3] = fmaxf(rmax[nt][3], c[mt][nt][3] + m2v[nt].y);
                }
            } else sawz1 = true;
        }
    }

    // ---- cross-wm combine (2 groups) in staging smem
    float* red  = (float*)(sm + OFF_STG);            // [16][128]
    float* zbuf = (float*)(sm + OFF_STG + 16*128*4); // [2][16]
    __syncthreads();
    if (wn == 0 && qc == 0) {
        zbuf[wm*16 + qr]     = sawz0 ? 0.0f : -CUDART_INF_F;
        zbuf[wm*16 + qr + 8] = sawz1 ? 0.0f : -CUDART_INF_F;
    }
    if (wm == 1) {
        #pragma unroll
        for (int nt = 0; nt < 4; nt++) {
            #pragma unroll
            for (int q = 0; q < 4; q++) {
                int recv = qr + (q >> 1)*8;
                int col  = wn*32 + nt*8 + 2*qc + (q & 1);
                red[recv*128 + col] = rmax[nt][q];
            }
        }
    }
    __syncthreads();
    if (wm == 0) {
        #pragma unroll
        for (int q2 = 0; q2 < 2; q2++) {
            const int recv = qr + q2*8;
            const int j = j0 + recv;
            const float z = fmaxf(zbuf[recv], zbuf[16 + recv]);
            #pragma unroll
            for (int nt = 0; nt < 4; nt++) {
                const int col = wn*32 + nt*8 + 2*qc;
                float v0 = fmaxf(rmax[nt][q2*2 + 0], red[recv*128 + col]);
                float v1 = fmaxf(rmax[nt][q2*2 + 1], red[recv*128 + col + 1]);
                float2 m1 = *(const float2*)(&g_M1c[((size_t)b*NN + j)*DD + col]);
                float2 o;
                o.x = fmaxf(v0 + m1.x, z);
                o.y = fmaxf(v1 + m1.y, z);
                *(float2*)(&g_part[(((size_t)ig*BB + b)*NN + j)*DD + col]) = o;
            }
        }
    }
}

// -------- output head: reduce partials + Wo2 GEMM, 4 rows per block --------
__global__ void k_final(const float* __restrict__ Wo2, const float* __restrict__ bo2,
                        float* __restrict__ ret) {
    __shared__ float ms[4][DD];
    const int row0 = blockIdx.x * 4;
    const int t = threadIdx.x;      // 128
    #pragma unroll
    for (int r = 0; r < 4; r++) {
        float v = -CUDART_INF_F;
        #pragma unroll
        for (int g = 0; g < IGRP; g++)
            v = fmaxf(v, g_part[(size_t)g*BB*NN*DD + (size_t)(row0 + r)*DD + t]);
        ms[r][t] = v;
    }
    __syncthreads();
    float acc[4];
    const float bia = bo2[t];
    #pragma unroll
    for (int r = 0; r < 4; r++) acc[r] = g_o1[(row0 + r)*DD + t] + bia;
    for (int k = 0; k < DD; k++) {
        float w = Wo2[k*DD + t];
        #pragma unroll
        for (int r = 0; r < 4; r++) acc[r] += ms[r][k] * w;
    }
    #pragma unroll
    for (int r = 0; r < 4; r++) ret[(row0 + r)*DD + t] = acc[r];
}

extern "C" void kernel_launch(void* const* d_in, const int* in_sizes, int n_in,
                              void* d_out, int out_size) {
    (void)in_sizes; (void)n_in; (void)out_size;
    const float* node   = (const float*)d_in[0];
    const float* edge   = (const float*)d_in[1];
    const float* graph  = (const float*)d_in[2];
    const float* adj    = (const float*)d_in[3];
    const float* hidden = (const float*)d_in[4];
    const float* Wm1 = (const float*)d_in[5],  *bm1 = (const float*)d_in[6];
    const float* Wm2 = (const float*)d_in[7],  *bm2 = (const float*)d_in[8];
    const float* Wme = (const float*)d_in[9],  *bme = (const float*)d_in[10];
    const float* Wmg = (const float*)d_in[11], *bmg = (const float*)d_in[12];
    const float* Wo1 = (const float*)d_in[13], *bo1 = (const float*)d_in[14];
    const float* Wo2 = (const float*)d_in[15], *bo2 = (const float*)d_in[16];
    const float* Wt1 = (const float*)d_in[17], *bt1 = (const float*)d_in[18];
    const float* Wt2 = (const float*)d_in[19], *bt2 = (const float*)d_in[20];
    const float* Wte = (const float*)d_in[21], *bte = (const float*)d_in[22];
    const float* Wtg = (const float*)d_in[23], *btg = (const float*)d_in[24];

    float* ret = (float*)d_out;
    float* tri = (float*)d_out + (size_t)BB*NN*DD;

    cudaFuncSetAttribute(k_main, cudaFuncAttributeMaxDynamicSharedMemorySize, SMEM_MAIN);

    k_graph<<<BB, 128>>>(graph, Wmg, bmg, Wtg, btg);
    k_node<<<BB*NN/8, 128>>>(node, hidden, Wm1, bm1, Wm2, bm2, bme,
                             Wo1, bo1, Wt1, bt1, Wt2, bt2, bte);
    for (int ig_base = 0; ig_base < IGRP; ig_base += 2)
        k_main<<<dim3(NN/TJ, 2, BB), NTH, SMEM_MAIN>>>(edge, adj, Wme, Wte, tri, ig_base);
    k_final<<<BB*NN/4, 128>>>(Wo2, bo2, ret);
}

// round 11
// speedup vs baseline: 1.3455x; 1.0286x over previous
#include <cuda_runtime.h>
#include <cuda_bf16.h>
#include <math_constants.h>
#include <cstdint>

#define BB 2
#define NN 512
#define HH 128
#define DD 128
#define TT 8
#define ZZ 256

#define NTH 256
#define TJ 16             // receivers per tile
#define CI 8              // senders per chunk
#define ISPAN 64          // senders per block
#define IGRP (NN/ISPAN)   // 8 sender groups
#define NCHUNK (ISPAN/CI) // 8 chunks

#define ALD 136           // lead dim (bf16 elems)
#define BROW (ALD*2)      // 272 bytes per row
// ---- smem offsets (bytes) ----
#define OFF_BH   0
#define OFF_BL   34816
#define OFF_BTH  69632
#define OFF_BTL  71808
#define OFF_A    73984               // A[p]: hi at +p*69632, lo at +p*69632+34816
#define SMEM_MAIN (73984 + 2*69632) // 213248

// ---------------- scratch ----------------
__device__ float g_M1c[BB*NN*DD];
__device__ float g_M2 [BB*NN*DD];
__device__ float g_T1c[BB*NN*TT];
__device__ float g_T2 [BB*NN*TT];
__device__ float g_o1 [BB*NN*DD];
__device__ float g_part[IGRP*BB*NN*DD];

__device__ __forceinline__ uint32_t smem_u32(const void* p) {
    uint32_t a;
    asm("{ .reg .u64 t; cvta.to.shared.u64 t, %1; cvt.u32.u64 %0, t; }" : "=r"(a) : "l"(p));
    return a;
}
__device__ __forceinline__ void cvt_hilo(float x, float y, unsigned &hi, unsigned &lo) {
    unsigned bx = __float_as_uint(x) & 0xFFFF0000u;
    unsigned by = __float_as_uint(y) & 0xFFFF0000u;
    hi = __byte_perm(bx, by, 0x7632);
    float lx = x - __uint_as_float(bx);
    float ly = y - __uint_as_float(by);
    asm("cvt.rn.bf16x2.f32 %0, %1, %2;" : "=r"(lo) : "f"(ly), "f"(lx));
}
__device__ __forceinline__ void mma16816(float* c, const uint32_t* a, uint32_t b0, uint32_t b1) {
    asm volatile(
        "mma.sync.aligned.m16n8k16.row.col.f32.bf16.bf16.f32 "
        "{%0,%1,%2,%3}, {%4,%5,%6,%7}, {%8,%9}, {%0,%1,%2,%3};"
        : "+f"(c[0]), "+f"(c[1]), "+f"(c[2]), "+f"(c[3])
        : "r"(a[0]), "r"(a[1]), "r"(a[2]), "r"(a[3]), "r"(b0), "r"(b1));
}
#define LDMX4(r0,r1,r2,r3,addr) \
    asm volatile("ldmatrix.sync.aligned.m8n8.x4.shared.b16 {%0,%1,%2,%3}, [%4];" \
        : "=r"(r0),"=r"(r1),"=r"(r2),"=r"(r3) : "r"(addr))
#define LDMX2(r0,r1,addr) \
    asm volatile("ldmatrix.sync.aligned.m8n8.x2.shared.b16 {%0,%1}, [%2];" \
        : "=r"(r0),"=r"(r1) : "r"(addr))

// -------- per-node precompute (graph terms inlined): 8 rows per block --------
__global__ void k_node(const float* __restrict__ node, const float* __restrict__ hidden,
                       const float* __restrict__ graph_fts,
                       const float* __restrict__ Wmg, const float* __restrict__ bmg,
                       const float* __restrict__ Wtg, const float* __restrict__ btg,
                       const float* __restrict__ Wm1, const float* __restrict__ bm1,
                       const float* __restrict__ Wm2, const float* __restrict__ bm2,
                       const float* __restrict__ bme,
                       const float* __restrict__ Wo1, const float* __restrict__ bo1,
                       const float* __restrict__ Wt1, const float* __restrict__ bt1,
                       const float* __restrict__ Wt2, const float* __restrict__ bt2,
                       const float* __restrict__ bte) {
    __shared__ float zs[8][ZZ];
    __shared__ float gs[HH];
    const int row0 = blockIdx.x * 8;
    const int b    = row0 / NN;
    const int t    = threadIdx.x;   // 128
    gs[t] = graph_fts[b*HH + t];
    #pragma unroll
    for (int r = 0; r < 8; r++) {
        zs[r][t]      = node[(row0 + r)*HH + t];
        zs[r][HH + t] = hidden[(row0 + r)*HH + t];
    }
    __syncthreads();
    // graph terms (redundant per block; trivial)
    float gm = bmg[t];
    #pragma unroll 4
    for (int k = 0; k < HH; k++) gm += gs[k] * Wmg[k*DD + t];

    float a1[8], a2[8], a3[8];
    const float bia = bm1[t] + bm2[t] + bme[t] + gm;
    const float bio = bo1[t];
    #pragma unroll
    for (int r = 0; r < 8; r++) { a1[r] = bia; a2[r] = 0.f; a3[r] = bio; }
    for (int k = 0; k < ZZ; k++) {
        float w1 = Wm1[k*DD + t], w2 = Wm2[k*DD + t], w3 = Wo1[k*DD + t];
        #pragma unroll
        for (int r = 0; r < 8; r++) {
            float zk = zs[r][k];
            a1[r] += zk*w1; a2[r] += zk*w2; a3[r] += zk*w3;
        }
    }
    #pragma unroll
    for (int r = 0; r < 8; r++) {
        g_M1c[(row0 + r)*DD + t] = a1[r];
        g_M2 [(row0 + r)*DD + t] = a2[r];
        g_o1 [(row0 + r)*DD + t] = a3[r];
    }
    {
        int r = t >> 4, which = (t >> 3) & 1, tt = t & 7;
        const float* W = which ? Wt2 : Wt1;
        float a;
        if (which) a = 0.f;
        else {
            float tg = btg[tt];
            #pragma unroll 4
            for (int k = 0; k < HH; k++) tg += gs[k] * Wtg[k*TT + tt];
            a = bt1[tt] + bt2[tt] + bte[tt] + tg;
        }
        #pragma unroll 4
        for (int k = 0; k < ZZ; k++) a += zs[r][k] * W[k*TT + tt];
        if (which) g_T2 [(row0 + r)*TT + tt] = a;
        else       g_T1c[(row0 + r)*TT + tt] = a;
    }
}

// -------- fused edge GEMM: MMA overlapped with next-chunk convert --------
__global__ void __launch_bounds__(NTH, 1)
k_main(const float* __restrict__ edge, const float* __restrict__ adj,
       const float* __restrict__ Wme, const float* __restrict__ Wte,
       float* __restrict__ tri_out) {
    extern __shared__ char sm[];
    const uint32_t smb = smem_u32(sm);
    const int tid  = threadIdx.x;
    const int lane = tid & 31, wid = tid >> 5;
    const int qr   = lane >> 2, qc = lane & 3;
    const int wm   = wid >> 2, wn = wid & 3;     // 2m x 4n warp grid, m64 x n32 per warp
    const int jb   = blockIdx.x, ig = blockIdx.y, b = blockIdx.z;
    const int j0   = jb * TJ;
    const int i0   = ig * ISPAN;
    const size_t ebase = ((size_t)b*NN)*NN*HH;

    // per-thread convert addressing: 16 float4 per chunk, s = 0..15, F4 = s*256+tid
    const int cv_e = ((tid >> 5) | 0);     // partial; full e depends on s — computed inline

    // ---- convert B = Wme -> [n][k] bf16 hi/lo
    for (int idx = tid; idx < HH*DD; idx += NTH) {
        int k = idx >> 7, n = idx & 127;
        float w = Wme[idx];
        unsigned bw = __float_as_uint(w) & 0xFFFF0000u;
        *(unsigned short*)(sm + OFF_BH + n*BROW + k*2) = (unsigned short)(bw >> 16);
        *(__nv_bfloat16*)(sm + OFF_BL + n*BROW + k*2) = __float2bfloat16(w - __uint_as_float(bw));
    }
    for (int idx = tid; idx < HH*TT; idx += NTH) {
        int k = idx >> 3, n = idx & 7;
        float w = Wte[idx];
        unsigned bw = __float_as_uint(w) & 0xFFFF0000u;
        *(unsigned short*)(sm + OFF_BTH + n*BROW + k*2) = (unsigned short)(bw >> 16);
        *(__nv_bfloat16*)(sm + OFF_BTL + n*BROW + k*2) = __float2bfloat16(w - __uint_as_float(bw));
    }

    // ---- prologue: convert chunk 0 into buffer 0 (exposed once)
    {
        #pragma unroll
        for (int s = 0; s < 16; s++) {
            int F4 = s*NTH + tid;
            int e = F4 >> 5, k = (F4 & 31) << 2;
            int di = e >> 4, dj = e & 15;
            float4 v = *(const float4*)(edge + ebase + ((size_t)(i0 + di)*NN + (j0 + dj))*(size_t)HH + k);
            unsigned h01, l01, h23, l23;
            cvt_hilo(v.x, v.y, h01, l01);
            cvt_hilo(v.z, v.w, h23, l23);
            *(uint2*)(sm + OFF_A + e*BROW + k*2)         = make_uint2(h01, h23);
            *(uint2*)(sm + OFF_A + 34816 + e*BROW + k*2) = make_uint2(l01, l23);
        }
    }

    // fragment lane offsets (same scheme as passing rounds)
    const uint32_t aoff  = (uint32_t)((wm*64 + (lane & 15))*BROW + (((lane >> 4) << 3)) * 2);
    const uint32_t boff  = (uint32_t)((wn*32 + ((lane >> 4) << 3) + (lane & 7))*BROW + ((((lane >> 3) & 1) << 3)) * 2);
    const uint32_t btoff = (uint32_t)((lane & 7)*BROW + ((((lane >> 3) & 1) << 3)) * 2);
    const uint32_t bHb = smb + OFF_BH + boff,  bLb = smb + OFF_BL + boff;
    const uint32_t tHb = smb + OFF_BTH + btoff, tLb = smb + OFF_BTL + btoff;

    // hoisted T1 (receiver-side, chunk-invariant)
    const int ja = j0 + qr, jb2 = j0 + qr + 8;
    const float2 t1a = *(const float2*)(&g_T1c[((size_t)b*NN + ja )*TT + 2*qc]);
    const float2 t1b = *(const float2*)(&g_T1c[((size_t)b*NN + jb2)*TT + 2*qc]);

    float rmax[4][4];
    #pragma unroll
    for (int nt = 0; nt < 4; nt++)
        #pragma unroll
        for (int q = 0; q < 4; q++) rmax[nt][q] = -CUDART_INF_F;
    bool sawz0 = false, sawz1 = false;

    __syncthreads();   // buffer 0 ready

    for (int ci = 0; ci < NCHUNK; ci++) {
        const int i0c = i0 + ci*CI;
        const int p = ci & 1;
        const bool conv = (ci + 1 < NCHUNK);
        const int i0n = i0c + CI;
        const uint32_t aHb = smb + OFF_A + p*69632 + aoff;
        const uint32_t aLb = aHb + 34816;
        char* dstH = sm + OFF_A + (1-p)*69632;
        char* dstL = dstH + 34816;

        // prefetch adjacency for this chunk's epilogue (8 LDG, consumed ~6K cyc later)
        float a0v[4], a1v[4];
        #pragma unroll
        for (int mt = 0; mt < 4; mt++) {
            const int i = i0c + wm*4 + mt;
            a0v[mt] = adj[((size_t)b*NN + i)*NN + j0 + qr];
            a1v[mt] = adj[((size_t)b*NN + i)*NN + j0 + qr + 8];
        }

        // register pipeline for next-chunk loads (2 float4 per ks)
        float4 v[2][2];
        if (conv) {
            #pragma unroll
            for (int u = 0; u < 2; u++) {
                int F4 = u*NTH + tid;
                int e = F4 >> 5, k = (F4 & 31) << 2;
                v[0][u] = *(const float4*)(edge + ebase + ((size_t)(i0n + (e>>4))*NN + (j0 + (e&15)))*(size_t)HH + k);
            }
        }

        float c[4][4][4];
        float ct[4] = {0.f, 0.f, 0.f, 0.f};
        #pragma unroll
        for (int mt = 0; mt < 4; mt++)
            #pragma unroll
            for (int nt = 0; nt < 4; nt++)
                #pragma unroll
                for (int q = 0; q < 4; q++) c[mt][nt][q] = 0.f;

        #pragma unroll
        for (int ks = 0; ks < 8; ks++) {
            // issue loads for ks+1 (land during this iteration's MMAs)
            if (conv && ks < 7) {
                #pragma unroll
                for (int u = 0; u < 2; u++) {
                    int F4 = (2*ks + 2 + u)*NTH + tid;
                    int e = F4 >> 5, k = (F4 & 31) << 2;
                    v[(ks+1)&1][u] = *(const float4*)(edge + ebase + ((size_t)(i0n + (e>>4))*NN + (j0 + (e&15)))*(size_t)HH + k);
                }
            }
            const uint32_t kb = ks * 32;
            uint32_t bH[2][4], bL[2][4];
            LDMX4(bH[0][0], bH[0][1], bH[0][2], bH[0][3], bHb + kb);
            LDMX4(bH[1][0], bH[1][1], bH[1][2], bH[1][3], bHb + 16*BROW + kb);
            LDMX4(bL[0][0], bL[0][1], bL[0][2], bL[0][3], bLb + kb);
            LDMX4(bL[1][0], bL[1][1], bL[1][2], bL[1][3], bLb + 16*BROW + kb);
            uint32_t t0h, t1h, t0l, t1l;
            LDMX2(t0h, t1h, tHb + kb);
            LDMX2(t0l, t1l, tLb + kb);
            #pragma unroll
            for (int mt = 0; mt < 4; mt++) {
                uint32_t aH[4], aL[4];
                LDMX4(aH[0], aH[1], aH[2], aH[3], aHb + mt*16*BROW + kb);
                LDMX4(aL[0], aL[1], aL[2], aL[3], aLb + mt*16*BROW + kb);
                #pragma unroll
                for (int nt = 0; nt < 4; nt++) {
                    uint32_t b0h = bH[nt>>1][(nt&1)*2], b1h = bH[nt>>1][(nt&1)*2+1];
                    uint32_t b0l = bL[nt>>1][(nt&1)*2], b1l = bL[nt>>1][(nt&1)*2+1];
                    mma16816(c[mt][nt], aH, b0h, b1h);
                    mma16816(c[mt][nt], aH, b0l, b1l);
                    mma16816(c[mt][nt], aL, b0h, b1h);
                }
                if (mt == wn) {
                    mma16816(ct, aH, t0h, t1h);
                    mma16816(ct, aH, t0l, t1l);
                    mma16816(ct, aL, t0h, t1h);
                }
            }
            // convert the data loaded 1 iteration ago into the other buffer
            if (conv) {
                #pragma unroll
                for (int u = 0; u < 2; u++) {
                    int F4 = (2*ks + u)*NTH + tid;
                    int e = F4 >> 5, k = (F4 & 31) << 2;
                    unsigned h01, l01, h23, l23;
                    cvt_hilo(v[ks&1][u].x, v[ks&1][u].y, h01, l01);
                    cvt_hilo(v[ks&1][u].z, v[ks&1][u].w, h23, l23);
                    *(uint2*)(dstH + e*BROW + k*2) = make_uint2(h01, h23);
                    *(uint2*)(dstL + e*BROW + k*2) = make_uint2(l01, l23);
                }
            }
        }

        // ---- register epilogue: tri write (sender i = i0c + wm*4 + wn)
        {
            const int i  = i0c + wm*4 + wn;
            const float2 t2v = *(const float2*)(&g_T2[((size_t)b*NN + i)*TT + 2*qc]);
            float2 oa, ob;
            oa.x = fmaxf(ct[0] + t1a.x + t2v.x, 0.f);
            oa.y = fmaxf(ct[1] + t1a.y + t2v.y, 0.f);
            ob.x = fmaxf(ct[2] + t1b.x + t2v.x, 0.f);
            ob.y = fmaxf(ct[3] + t1b.y + t2v.y, 0.f);
            *(float2*)(tri_out + (((size_t)b*NN + i)*NN + ja )*(size_t)TT + 2*qc) = oa;
            *(float2*)(tri_out + (((size_t)b*NN + i)*NN + jb2)*(size_t)TT + 2*qc) = ob;
        }
        // ---- register epilogue: masked max
        #pragma unroll
        for (int mt = 0; mt < 4; mt++) {
            const int i = i0c + wm*4 + mt;
            float2 m2v[4];
            #pragma unroll
            for (int nt = 0; nt < 4; nt++)
                m2v[nt] = *(const float2*)(&g_M2[((size_t)b*NN + i)*DD + wn*32 + nt*8 + 2*qc]);
            if (a0v[mt] != 0.0f) {
                #pragma unroll
                for (int nt = 0; nt < 4; nt++) {
                    rmax[nt][0] = fmaxf(rmax[nt][0], c[mt][nt][0] + m2v[nt].x);
                    rmax[nt][1] = fmaxf(rmax[nt][1], c[mt][nt][1] + m2v[nt].y);
                }
            } else sawz0 = true;
            if (a1v[mt] != 0.0f) {
                #pragma unroll
                for (int nt = 0; nt < 4; nt++) {
                    rmax[nt][2] = fmaxf(rmax[nt][2], c[mt][nt][2] + m2v[nt].x);
                    rmax[nt][3] = fmaxf(rmax[nt][3], c[mt][nt][3] + m2v[nt].y);
                }
            } else sawz1 = true;
        }

        __syncthreads();   // buffer 1-p fully written; buffer p reads done
    }

    // ---- cross-wm combine (2 groups) in now-dead A smem
    float* red  = (float*)(sm + OFF_A);            // [16][128]
    float* zbuf = (float*)(sm + OFF_A + 16*128*4); // [2][16]
    if (wn == 0 && qc == 0) {
        zbuf[wm*16 + qr]     = sawz0 ? 0.0f : -CUDART_INF_F;
        zbuf[wm*16 + qr + 8] = sawz1 ? 0.0f : -CUDART_INF_F;
    }
    if (wm == 1) {
        #pragma unroll
        for (int nt = 0; nt < 4; nt++) {
            #pragma unroll
            for (int q = 0; q < 4; q++) {
                int recv = qr + (q >> 1)*8;
                int col  = wn*32 + nt*8 + 2*qc + (q & 1);
                red[recv*128 + col] = rmax[nt][q];
            }
        }
    }
    __syncthreads();
    if (wm == 0) {
        #pragma unroll
        for (int q2 = 0; q2 < 2; q2++) {
            const int recv = qr + q2*8;
            const int j = j0 + recv;
            const float z = fmaxf(zbuf[recv], zbuf[16 + recv]);
            #pragma unroll
            for (int nt = 0; nt < 4; nt++) {
                const int col = wn*32 + nt*8 + 2*qc;
                float v0 = fmaxf(rmax[nt][q2*2 + 0], red[recv*128 + col]);
                float v1 = fmaxf(rmax[nt][q2*2 + 1], red[recv*128 + col + 1]);
                float2 m1 = *(const float2*)(&g_M1c[((size_t)b*NN + j)*DD + col]);
                float2 o;
                o.x = fmaxf(v0 + m1.x, z);
                o.y = fmaxf(v1 + m1.y, z);
                *(float2*)(&g_part[(((size_t)ig*BB + b)*NN + j)*DD + col]) = o;
            }
        }
    }
}

// -------- output head: reduce partials + Wo2 GEMM, 4 rows per block --------
__global__ void k_final(const float* __restrict__ Wo2, const float* __restrict__ bo2,
                        float* __restrict__ ret) {
    __shared__ float ms[4][DD];
    const int row0 = blockIdx.x * 4;
    const int t = threadIdx.x;      // 128
    #pragma unroll
    for (int r = 0; r < 4; r++) {
        float v = -CUDART_INF_F;
        #pragma unroll
        for (int g = 0; g < IGRP; g++)
            v = fmaxf(v, g_part[(size_t)g*BB*NN*DD + (size_t)(row0 + r)*DD + t]);
        ms[r][t] = v;
    }
    __syncthreads();
    float acc[4];
    const float bia = bo2[t];
    #pragma unroll
    for (int r = 0; r < 4; r++) acc[r] = g_o1[(row0 + r)*DD + t] + bia;
    for (int k = 0; k < DD; k++) {
        float w = Wo2[k*DD + t];
        #pragma unroll
        for (int r = 0; r < 4; r++) acc[r] += ms[r][k] * w;
    }
    #pragma unroll
    for (int r = 0; r < 4; r++) ret[(row0 + r)*DD + t] = acc[r];
}

extern "C" void kernel_launch(void* const* d_in, const int* in_sizes, int n_in,
                              void* d_out, int out_size) {
    (void)in_sizes; (void)n_in; (void)out_size;
    const float* node   = (const float*)d_in[0];
    const float* edge   = (const float*)d_in[1];
    const float* graph  = (const float*)d_in[2];
    const float* adj    = (const float*)d_in[3];
    const float* hidden = (const float*)d_in[4];
    const float* Wm1 = (const float*)d_in[5],  *bm1 = (const float*)d_in[6];
    const float* Wm2 = (const float*)d_in[7],  *bm2 = (const float*)d_in[8];
    const float* Wme = (const float*)d_in[9],  *bme = (const float*)d_in[10];
    const float* Wmg = (const float*)d_in[11], *bmg = (const float*)d_in[12];
    const float* Wo1 = (const float*)d_in[13], *bo1 = (const float*)d_in[14];
    const float* Wo2 = (const float*)d_in[15], *bo2 = (const float*)d_in[16];
    const float* Wt1 = (const float*)d_in[17], *bt1 = (const float*)d_in[18];
    const float* Wt2 = (const float*)d_in[19], *bt2 = (const float*)d_in[20];
    const float* Wte = (const float*)d_in[21], *bte = (const float*)d_in[22];
    const float* Wtg = (const float*)d_in[23], *btg = (const float*)d_in[24];

    float* ret = (float*)d_out;
    float* tri = (float*)d_out + (size_t)BB*NN*DD;

    cudaFuncSetAttribute(k_main, cudaFuncAttributeMaxDynamicSharedMemorySize, SMEM_MAIN);

    k_node<<<BB*NN/8, 128>>>(node, hidden, graph, Wmg, bmg, Wtg, btg,
                             Wm1, bm1, Wm2, bm2, bme,
                             Wo1, bo1, Wt1, bt1, Wt2, bt2, bte);
    k_main<<<dim3(NN/TJ, IGRP, BB), NTH, SMEM_MAIN>>>(edge, adj, Wme, Wte, tri);
    k_final<<<BB*NN/4, 128>>>(Wo2, bo2, ret);
}

// round 12
// speedup vs baseline: 1.3802x; 1.0258x over previous
#include <cuda_runtime.h>
#include <cuda_bf16.h>
#include <math_constants.h>
#include <cstdint>

#define BB 2
#define NN 512
#define HH 128
#define DD 128
#define TT 8
#define ZZ 256

#define NTH 256
#define TJ 16             // receivers per tile
#define CI 8              // senders per chunk
#define ISPAN 64          // senders per block
#define IGRP (NN/ISPAN)   // 8 sender groups
#define NCHUNK (ISPAN/CI) // 8 chunks

#define ALD 136           // lead dim (bf16 elems)
#define BROW (ALD*2)      // 272 bytes per row
// ---- smem offsets (bytes) ----
#define OFF_BH   0
#define OFF_BL   34816
#define OFF_BTH  69632
#define OFF_BTL  71808
#define OFF_A    73984               // A[p]: hi at +p*69632, lo at +p*69632+34816
#define SMEM_MAIN (73984 + 2*69632) // 213248

// ---------------- scratch ----------------
__device__ float g_M1c[BB*NN*DD];
__device__ float g_M2 [BB*NN*DD];
__device__ float g_T1c[BB*NN*TT];
__device__ float g_T2 [BB*NN*TT];
__device__ float g_o1 [BB*NN*DD];
__device__ float g_part[IGRP*BB*NN*DD];

__device__ __forceinline__ uint32_t smem_u32(const void* p) {
    uint32_t a;
    asm("{ .reg .u64 t; cvta.to.shared.u64 t, %1; cvt.u32.u64 %0, t; }" : "=r"(a) : "l"(p));
    return a;
}
__device__ __forceinline__ void cvt_hilo(float x, float y, unsigned &hi, unsigned &lo) {
    unsigned bx = __float_as_uint(x) & 0xFFFF0000u;
    unsigned by = __float_as_uint(y) & 0xFFFF0000u;
    hi = __byte_perm(bx, by, 0x7632);
    float lx = x - __uint_as_float(bx);
    float ly = y - __uint_as_float(by);
    asm("cvt.rn.bf16x2.f32 %0, %1, %2;" : "=r"(lo) : "f"(ly), "f"(lx));
}
__device__ __forceinline__ void mma16816(float* c, const uint32_t* a, uint32_t b0, uint32_t b1) {
    asm volatile(
        "mma.sync.aligned.m16n8k16.row.col.f32.bf16.bf16.f32 "
        "{%0,%1,%2,%3}, {%4,%5,%6,%7}, {%8,%9}, {%0,%1,%2,%3};"
        : "+f"(c[0]), "+f"(c[1]), "+f"(c[2]), "+f"(c[3])
        : "r"(a[0]), "r"(a[1]), "r"(a[2]), "r"(a[3]), "r"(b0), "r"(b1));
}
#define LDMX4(r0,r1,r2,r3,addr) \
    asm volatile("ldmatrix.sync.aligned.m8n8.x4.shared.b16 {%0,%1,%2,%3}, [%4];" \
        : "=r"(r0),"=r"(r1),"=r"(r2),"=r"(r3) : "r"(addr))
#define LDMX2(r0,r1,addr) \
    asm volatile("ldmatrix.sync.aligned.m8n8.x2.shared.b16 {%0,%1}, [%2];" \
        : "=r"(r0),"=r"(r1) : "r"(addr))

// -------- per-node precompute: 4 rows/block, 256 threads, unrolled --------
__global__ void __launch_bounds__(256)
k_node(const float* __restrict__ node, const float* __restrict__ hidden,
       const float* __restrict__ graph_fts,
       const float* __restrict__ Wmg, const float* __restrict__ bmg,
       const float* __restrict__ Wtg, const float* __restrict__ btg,
       const float* __restrict__ Wm1, const float* __restrict__ bm1,
       const float* __restrict__ Wm2, const float* __restrict__ bm2,
       const float* __restrict__ bme,
       const float* __restrict__ Wo1, const float* __restrict__ bo1,
       const float* __restrict__ Wt1, const float* __restrict__ bt1,
       const float* __restrict__ Wt2, const float* __restrict__ bt2,
       const float* __restrict__ bte) {
    __shared__ float zs[4][ZZ];
    __shared__ float gs[HH];
    const int row0 = blockIdx.x * 4;
    const int b    = row0 / NN;
    const int tid  = threadIdx.x;        // 256
    const int half = tid >> 7;           // 0/1 -> rows {0,1} / {2,3}
    const int t    = tid & 127;          // output column

    if (tid < HH) gs[tid] = graph_fts[b*HH + tid];
    for (int x = tid; x < 4*ZZ; x += 256) {
        int r = x >> 8, k = x & 255;
        zs[r][k] = (k < HH) ? node[(row0 + r)*HH + k]
                            : hidden[(row0 + r)*HH + (k - HH)];
    }
    __syncthreads();

    // graph term for this column (both halves compute the same value)
    float gm = bmg[t];
    #pragma unroll 8
    for (int k = 0; k < HH; k++) gm += gs[k] * Wmg[k*DD + t];

    const int r0 = half*2;
    float a1[2], a2[2], a3[2];
    const float bia = bm1[t] + bm2[t] + bme[t] + gm;
    const float bio = bo1[t];
    #pragma unroll
    for (int rr = 0; rr < 2; rr++) { a1[rr] = bia; a2[rr] = 0.f; a3[rr] = bio; }

    #pragma unroll 4
    for (int k = 0; k < ZZ; k++) {
        float w1 = Wm1[k*DD + t], w2 = Wm2[k*DD + t], w3 = Wo1[k*DD + t];
        #pragma unroll
        for (int rr = 0; rr < 2; rr++) {
            float zk = zs[r0 + rr][k];
            a1[rr] += zk*w1; a2[rr] += zk*w2; a3[rr] += zk*w3;
        }
    }
    #pragma unroll
    for (int rr = 0; rr < 2; rr++) {
        g_M1c[(row0 + r0 + rr)*DD + t] = a1[rr];
        g_M2 [(row0 + r0 + rr)*DD + t] = a2[rr];
        g_o1 [(row0 + r0 + rr)*DD + t] = a3[rr];
    }

    // triplet heads: tid < 64 -> (r = tid>>4, which = (tid>>3)&1, tt = tid&7)
    if (tid < 64) {
        int r = tid >> 4, which = (tid >> 3) & 1, tt = tid & 7;
        const float* W = which ? Wt2 : Wt1;
        float a;
        if (which) a = 0.f;
        else {
            float tg = btg[tt];
            #pragma unroll 8
            for (int k = 0; k < HH; k++) tg += gs[k] * Wtg[k*TT + tt];
            a = bt1[tt] + bt2[tt] + bte[tt] + tg;
        }
        #pragma unroll 4
        for (int k = 0; k < ZZ; k++) a += zs[r][k] * W[k*TT + tt];
        if (which) g_T2 [(row0 + r)*TT + tt] = a;
        else       g_T1c[(row0 + r)*TT + tt] = a;
    }
}

// -------- fused edge GEMM: MMA overlapped with next-chunk convert --------
__global__ void __launch_bounds__(NTH, 1)
k_main(const float* __restrict__ edge, const float* __restrict__ adj,
       const float* __restrict__ Wme, const float* __restrict__ Wte,
       float* __restrict__ tri_out) {
    extern __shared__ char sm[];
    const uint32_t smb = smem_u32(sm);
    const int tid  = threadIdx.x;
    const int lane = tid & 31, wid = tid >> 5;
    const int qr   = lane >> 2, qc = lane & 3;
    const int wm   = wid >> 2, wn = wid & 3;     // 2m x 4n warp grid, m64 x n32 per warp
    const int jb   = blockIdx.x, ig = blockIdx.y, b = blockIdx.z;
    const int j0   = jb * TJ;
    const int i0   = ig * ISPAN;
    const size_t ebase = ((size_t)b*NN)*NN*HH;

    // ---- convert B = Wme -> [n][k] bf16 hi/lo
    for (int idx = tid; idx < HH*DD; idx += NTH) {
        int k = idx >> 7, n = idx & 127;
        float w = Wme[idx];
        unsigned bw = __float_as_uint(w) & 0xFFFF0000u;
        *(unsigned short*)(sm + OFF_BH + n*BROW + k*2) = (unsigned short)(bw >> 16);
        *(__nv_bfloat16*)(sm + OFF_BL + n*BROW + k*2) = __float2bfloat16(w - __uint_as_float(bw));
    }
    for (int idx = tid; idx < HH*TT; idx += NTH) {
        int k = idx >> 3, n = idx & 7;
        float w = Wte[idx];
        unsigned bw = __float_as_uint(w) & 0xFFFF0000u;
        *(unsigned short*)(sm + OFF_BTH + n*BROW + k*2) = (unsigned short)(bw >> 16);
        *(__nv_bfloat16*)(sm + OFF_BTL + n*BROW + k*2) = __float2bfloat16(w - __uint_as_float(bw));
    }

    // ---- prologue: convert chunk 0 into buffer 0 (exposed once)
    {
        #pragma unroll
        for (int s = 0; s < 16; s++) {
            int F4 = s*NTH + tid;
            int e = F4 >> 5, k = (F4 & 31) << 2;
            int di = e >> 4, dj = e & 15;
            float4 v = *(const float4*)(edge + ebase + ((size_t)(i0 + di)*NN + (j0 + dj))*(size_t)HH + k);
            unsigned h01, l01, h23, l23;
            cvt_hilo(v.x, v.y, h01, l01);
            cvt_hilo(v.z, v.w, h23, l23);
            *(uint2*)(sm + OFF_A + e*BROW + k*2)         = make_uint2(h01, h23);
            *(uint2*)(sm + OFF_A + 34816 + e*BROW + k*2) = make_uint2(l01, l23);
        }
    }

    // fragment lane offsets (same scheme as passing rounds)
    const uint32_t aoff  = (uint32_t)((wm*64 + (lane & 15))*BROW + (((lane >> 4) << 3)) * 2);
    const uint32_t boff  = (uint32_t)((wn*32 + ((lane >> 4) << 3) + (lane & 7))*BROW + ((((lane >> 3) & 1) << 3)) * 2);
    const uint32_t btoff = (uint32_t)((lane & 7)*BROW + ((((lane >> 3) & 1) << 3)) * 2);
    const uint32_t bHb = smb + OFF_BH + boff,  bLb = smb + OFF_BL + boff;
    const uint32_t tHb = smb + OFF_BTH + btoff, tLb = smb + OFF_BTL + btoff;

    // hoisted T1 (receiver-side, chunk-invariant)
    const int ja = j0 + qr, jb2 = j0 + qr + 8;
    const float2 t1a = *(const float2*)(&g_T1c[((size_t)b*NN + ja )*TT + 2*qc]);
    const float2 t1b = *(const float2*)(&g_T1c[((size_t)b*NN + jb2)*TT + 2*qc]);

    float rmax[4][4];
    #pragma unroll
    for (int nt = 0; nt < 4; nt++)
        #pragma unroll
        for (int q = 0; q < 4; q++) rmax[nt][q] = -CUDART_INF_F;
    bool sawz0 = false, sawz1 = false;

    __syncthreads();   // buffer 0 ready

    for (int ci = 0; ci < NCHUNK; ci++) {
        const int i0c = i0 + ci*CI;
        const int p = ci & 1;
        const bool conv = (ci + 1 < NCHUNK);
        const int i0n = i0c + CI;
        const uint32_t aHb = smb + OFF_A + p*69632 + aoff;
        const uint32_t aLb = aHb + 34816;
        char* dstH = sm + OFF_A + (1-p)*69632;
        char* dstL = dstH + 34816;

        // prefetch adjacency for this chunk's epilogue
        float a0v[4], a1v[4];
        #pragma unroll
        for (int mt = 0; mt < 4; mt++) {
            const int i = i0c + wm*4 + mt;
            a0v[mt] = adj[((size_t)b*NN + i)*NN + j0 + qr];
            a1v[mt] = adj[((size_t)b*NN + i)*NN + j0 + qr + 8];
        }

        // register pipeline for next-chunk loads (2 float4 per ks)
        float4 v[2][2];
        if (conv) {
            #pragma unroll
            for (int u = 0; u < 2; u++) {
                int F4 = u*NTH + tid;
                int e = F4 >> 5, k = (F4 & 31) << 2;
                v[0][u] = *(const float4*)(edge + ebase + ((size_t)(i0n + (e>>4))*NN + (j0 + (e&15)))*(size_t)HH + k);
            }
        }

        float c[4][4][4];
        float ct[4] = {0.f, 0.f, 0.f, 0.f};
        #pragma unroll
        for (int mt = 0; mt < 4; mt++)
            #pragma unroll
            for (int nt = 0; nt < 4; nt++)
                #pragma unroll
                for (int q = 0; q < 4; q++) c[mt][nt][q] = 0.f;

        #pragma unroll
        for (int ks = 0; ks < 8; ks++) {
            // issue loads for ks+1 (land during this iteration's MMAs)
            if (conv && ks < 7) {
                #pragma unroll
                for (int u = 0; u < 2; u++) {
                    int F4 = (2*ks + 2 + u)*NTH + tid;
                    int e = F4 >> 5, k = (F4 & 31) << 2;
                    v[(ks+1)&1][u] = *(const float4*)(edge + ebase + ((size_t)(i0n + (e>>4))*NN + (j0 + (e&15)))*(size_t)HH + k);
                }
            }
            const uint32_t kb = ks * 32;
            uint32_t bH[2][4], bL[2][4];
            LDMX4(bH[0][0], bH[0][1], bH[0][2], bH[0][3], bHb + kb);
            LDMX4(bH[1][0], bH[1][1], bH[1][2], bH[1][3], bHb + 16*BROW + kb);
            LDMX4(bL[0][0], bL[0][1], bL[0][2], bL[0][3], bLb + kb);
            LDMX4(bL[1][0], bL[1][1], bL[1][2], bL[1][3], bLb + 16*BROW + kb);
            uint32_t t0h, t1h, t0l, t1l;
            LDMX2(t0h, t1h, tHb + kb);
            LDMX2(t0l, t1l, tLb + kb);
            #pragma unroll
            for (int mt = 0; mt < 4; mt++) {
                uint32_t aH[4], aL[4];
                LDMX4(aH[0], aH[1], aH[2], aH[3], aHb + mt*16*BROW + kb);
                LDMX4(aL[0], aL[1], aL[2], aL[3], aLb + mt*16*BROW + kb);
                #pragma unroll
                for (int nt = 0; nt < 4; nt++) {
                    uint32_t b0h = bH[nt>>1][(nt&1)*2], b1h = bH[nt>>1][(nt&1)*2+1];
                    uint32_t b0l = bL[nt>>1][(nt&1)*2], b1l = bL[nt>>1][(nt&1)*2+1];
                    mma16816(c[mt][nt], aH, b0h, b1h);
                    mma16816(c[mt][nt], aH, b0l, b1l);
                    mma16816(c[mt][nt], aL, b0h, b1h);
                }
                if (mt == wn) {
                    mma16816(ct, aH, t0h, t1h);
                    mma16816(ct, aH, t0l, t1l);
                    mma16816(ct, aL, t0h, t1h);
                }
            }
            // convert the data loaded 1 iteration ago into the other buffer
            if (conv) {
                #pragma unroll
                for (int u = 0; u < 2; u++) {
                    int F4 = (2*ks + u)*NTH + tid;
                    int e = F4 >> 5, k = (F4 & 31) << 2;
                    unsigned h01, l01, h23, l23;
                    cvt_hilo(v[ks&1][u].x, v[ks&1][u].y, h01, l01);
                    cvt_hilo(v[ks&1][u].z, v[ks&1][u].w, h23, l23);
                    *(uint2*)(dstH + e*BROW + k*2) = make_uint2(h01, h23);
                    *(uint2*)(dstL + e*BROW + k*2) = make_uint2(l01, l23);
                }
            }
        }

        // ---- register epilogue: tri write (sender i = i0c + wm*4 + wn)
        {
            const int i  = i0c + wm*4 + wn;
            const float2 t2v = *(const float2*)(&g_T2[((size_t)b*NN + i)*TT + 2*qc]);
            float2 oa, ob;
            oa.x = fmaxf(ct[0] + t1a.x + t2v.x, 0.f);
            oa.y = fmaxf(ct[1] + t1a.y + t2v.y, 0.f);
            ob.x = fmaxf(ct[2] + t1b.x + t2v.x, 0.f);
            ob.y = fmaxf(ct[3] + t1b.y + t2v.y, 0.f);
            *(float2*)(tri_out + (((size_t)b*NN + i)*NN + ja )*(size_t)TT + 2*qc) = oa;
            *(float2*)(tri_out + (((size_t)b*NN + i)*NN + jb2)*(size_t)TT + 2*qc) = ob;
        }
        // ---- register epilogue: masked max
        #pragma unroll
        for (int mt = 0; mt < 4; mt++) {
            const int i = i0c + wm*4 + mt;
            float2 m2v[4];
            #pragma unroll
            for (int nt = 0; nt < 4; nt++)
                m2v[nt] = *(const float2*)(&g_M2[((size_t)b*NN + i)*DD + wn*32 + nt*8 + 2*qc]);
            if (a0v[mt] != 0.0f) {
                #pragma unroll
                for (int nt = 0; nt < 4; nt++) {
                    rmax[nt][0] = fmaxf(rmax[nt][0], c[mt][nt][0] + m2v[nt].x);
                    rmax[nt][1] = fmaxf(rmax[nt][1], c[mt][nt][1] + m2v[nt].y);
                }
            } else sawz0 = true;
            if (a1v[mt] != 0.0f) {
                #pragma unroll
                for (int nt = 0; nt < 4; nt++) {
                    rmax[nt][2] = fmaxf(rmax[nt][2], c[mt][nt][2] + m2v[nt].x);
                    rmax[nt][3] = fmaxf(rmax[nt][3], c[mt][nt][3] + m2v[nt].y);
                }
            } else sawz1 = true;
        }

        __syncthreads();   // buffer 1-p fully written; buffer p reads done
    }

    // ---- cross-wm combine (2 groups) in now-dead A smem
    float* red  = (float*)(sm + OFF_A);            // [16][128]
    float* zbuf = (float*)(sm + OFF_A + 16*128*4); // [2][16]
    if (wn == 0 && qc == 0) {
        zbuf[wm*16 + qr]     = sawz0 ? 0.0f : -CUDART_INF_F;
        zbuf[wm*16 + qr + 8] = sawz1 ? 0.0f : -CUDART_INF_F;
    }
    if (wm == 1) {
        #pragma unroll
        for (int nt = 0; nt < 4; nt++) {
            #pragma unroll
            for (int q = 0; q < 4; q++) {
                int recv = qr + (q >> 1)*8;
                int col  = wn*32 + nt*8 + 2*qc + (q & 1);
                red[recv*128 + col] = rmax[nt][q];
            }
        }
    }
    __syncthreads();
    if (wm == 0) {
        #pragma unroll
        for (int q2 = 0; q2 < 2; q2++) {
            const int recv = qr + q2*8;
            const int j = j0 + recv;
            const float z = fmaxf(zbuf[recv], zbuf[16 + recv]);
            #pragma unroll
            for (int nt = 0; nt < 4; nt++) {
                const int col = wn*32 + nt*8 + 2*qc;
                float v0 = fmaxf(rmax[nt][q2*2 + 0], red[recv*128 + col]);
                float v1 = fmaxf(rmax[nt][q2*2 + 1], red[recv*128 + col + 1]);
                float2 m1 = *(const float2*)(&g_M1c[((size_t)b*NN + j)*DD + col]);
                float2 o;
                o.x = fmaxf(v0 + m1.x, z);
                o.y = fmaxf(v1 + m1.y, z);
                *(float2*)(&g_part[(((size_t)ig*BB + b)*NN + j)*DD + col]) = o;
            }
        }
    }
}

// -------- output head: reduce partials + Wo2 GEMM, 4 rows per block --------
__global__ void k_final(const float* __restrict__ Wo2, const float* __restrict__ bo2,
                        float* __restrict__ ret) {
    __shared__ float ms[4][DD];
    const int row0 = blockIdx.x * 4;
    const int t = threadIdx.x;      // 128
    #pragma unroll
    for (int r = 0; r < 4; r++) {
        float v = -CUDART_INF_F;
        #pragma unroll
        for (int g = 0; g < IGRP; g++)
            v = fmaxf(v, g_part[(size_t)g*BB*NN*DD + (size_t)(row0 + r)*DD + t]);
        ms[r][t] = v;
    }
    __syncthreads();
    float acc[4];
    const float bia = bo2[t];
    #pragma unroll
    for (int r = 0; r < 4; r++) acc[r] = g_o1[(row0 + r)*DD + t] + bia;
    #pragma unroll 4
    for (int k = 0; k < DD; k++) {
        float w = Wo2[k*DD + t];
        #pragma unroll
        for (int r = 0; r < 4; r++) acc[r] += ms[r][k] * w;
    }
    #pragma unroll
    for (int r = 0; r < 4; r++) ret[(row0 + r)*DD + t] = acc[r];
}

extern "C" void kernel_launch(void* const* d_in, const int* in_sizes, int n_in,
                              void* d_out, int out_size) {
    (void)in_sizes; (void)n_in; (void)out_size;
    const float* node   = (const float*)d_in[0];
    const float* edge   = (const float*)d_in[1];
    const float* graph  = (const float*)d_in[2];
    const float* adj    = (const float*)d_in[3];
    const float* hidden = (const float*)d_in[4];
    const float* Wm1 = (const float*)d_in[5],  *bm1 = (const float*)d_in[6];
    const float* Wm2 = (const float*)d_in[7],  *bm2 = (const float*)d_in[8];
    const float* Wme = (const float*)d_in[9],  *bme = (const float*)d_in[10];
    const float* Wmg = (const float*)d_in[11], *bmg = (const float*)d_in[12];
    const float* Wo1 = (const float*)d_in[13], *bo1 = (const float*)d_in[14];
    const float* Wo2 = (const float*)d_in[15], *bo2 = (const float*)d_in[16];
    const float* Wt1 = (const float*)d_in[17], *bt1 = (const float*)d_in[18];
    const float* Wt2 = (const float*)d_in[19], *bt2 = (const float*)d_in[20];
    const float* Wte = (const float*)d_in[21], *bte = (const float*)d_in[22];
    const float* Wtg = (const float*)d_in[23], *btg = (const float*)d_in[24];

    float* ret = (float*)d_out;
    float* tri = (float*)d_out + (size_t)BB*NN*DD;

    cudaFuncSetAttribute(k_main, cudaFuncAttributeMaxDynamicSharedMemorySize, SMEM_MAIN);

    k_node<<<BB*NN/4, 256>>>(node, hidden, graph, Wmg, bmg, Wtg, btg,
                             Wm1, bm1, Wm2, bm2, bme,
                             Wo1, bo1, Wt1, bt1, Wt2, bt2, bte);
    k_main<<<dim3(NN/TJ, IGRP, BB), NTH, SMEM_MAIN>>>(edge, adj, Wme, Wte, tri);
    k_final<<<BB*NN/4, 128>>>(Wo2, bo2, ret);
}

// round 13
// speedup vs baseline: 1.8538x; 1.3432x over previous
#include <cuda_runtime.h>
#include <cuda_bf16.h>
#include <math_constants.h>
#include <cstdint>

#define BB 2
#define NN 512
#define HH 128
#define DD 128
#define TT 8
#define ZZ 256

#define NTH 256
#define TJ 16             // receivers per tile
#define CI 8              // senders per chunk
#define ISPAN 64          // senders per block
#define IGRP (NN/ISPAN)   // 8 sender groups
#define NCHUNK (ISPAN/CI) // 8 chunks

#define ALD 136           // lead dim (bf16 elems)
#define BROW (ALD*2)      // 272 bytes per row
// ---- k_main smem offsets (bytes) ----
#define OFF_BH   0
#define OFF_BL   34816
#define OFF_BTH  69632
#define OFF_BTL  71808
#define OFF_A    73984               // A[p]: hi at +p*69632, lo at +p*69632+34816
#define SMEM_MAIN (73984 + 2*69632) // 213248

// ---- k_node smem (floats) ----
#define KT 32
#define NODE_SW_FLOATS (2*3*KT*DD)          // 24576
#define NODE_WT_OFF    NODE_SW_FLOATS       // Wt1 2048, Wt2 2048
#define NODE_ZS_OFF    (NODE_SW_FLOATS + 4096)
#define NODE_SMEM_B    ((NODE_ZS_OFF + 8*ZZ) * 4)   // 122880 B

// ---- k_final smem (floats) ----
#define FIN_MS_OFF  (DD*DD)                 // Wo2 16384 floats, then ms 4*128
#define FIN_SMEM_B  ((DD*DD + 4*DD) * 4)    // 67584 B

// ---------------- scratch ----------------
__device__ float g_M1c[BB*NN*DD];
__device__ float g_M2 [BB*NN*DD];
__device__ float g_T1c[BB*NN*TT];
__device__ float g_T2 [BB*NN*TT];
__device__ float g_o1 [BB*NN*DD];
__device__ float g_gm [BB*DD];
__device__ float g_tg [BB*TT];
__device__ float g_part[IGRP*BB*NN*DD];

__device__ __forceinline__ uint32_t smem_u32(const void* p) {
    uint32_t a;
    asm("{ .reg .u64 t; cvta.to.shared.u64 t, %1; cvt.u32.u64 %0, t; }" : "=r"(a) : "l"(p));
    return a;
}
__device__ __forceinline__ void cvt_hilo(float x, float y, unsigned &hi, unsigned &lo) {
    unsigned bx = __float_as_uint(x) & 0xFFFF0000u;
    unsigned by = __float_as_uint(y) & 0xFFFF0000u;
    hi = __byte_perm(bx, by, 0x7632);
    float lx = x - __uint_as_float(bx);
    float ly = y - __uint_as_float(by);
    asm("cvt.rn.bf16x2.f32 %0, %1, %2;" : "=r"(lo) : "f"(ly), "f"(lx));
}
__device__ __forceinline__ void mma16816(float* c, const uint32_t* a, uint32_t b0, uint32_t b1) {
    asm volatile(
        "mma.sync.aligned.m16n8k16.row.col.f32.bf16.bf16.f32 "
        "{%0,%1,%2,%3}, {%4,%5,%6,%7}, {%8,%9}, {%0,%1,%2,%3};"
        : "+f"(c[0]), "+f"(c[1]), "+f"(c[2]), "+f"(c[3])
        : "r"(a[0]), "r"(a[1]), "r"(a[2]), "r"(a[3]), "r"(b0), "r"(b1));
}
#define LDMX4(r0,r1,r2,r3,addr) \
    asm volatile("ldmatrix.sync.aligned.m8n8.x4.shared.b16 {%0,%1,%2,%3}, [%4];" \
        : "=r"(r0),"=r"(r1),"=r"(r2),"=r"(r3) : "r"(addr))
#define LDMX2(r0,r1,addr) \
    asm volatile("ldmatrix.sync.aligned.m8n8.x2.shared.b16 {%0,%1}, [%2];" \
        : "=r"(r0),"=r"(r1) : "r"(addr))
#define CP_ASYNC16(dst, src) \
    asm volatile("cp.async.cg.shared.global [%0], [%1], 16;" :: "r"(dst), "l"(src) : "memory")
#define CP_COMMIT() asm volatile("cp.async.commit_group;" ::: "memory")
#define CP_WAIT0()  asm volatile("cp.async.wait_group 0;" ::: "memory")
#define CP_WAIT1()  asm volatile("cp.async.wait_group 1;" ::: "memory")

// -------- graph-level terms (once, 2 blocks) --------
__global__ void k_graph(const float* __restrict__ graph_fts,
                        const float* __restrict__ Wmg, const float* __restrict__ bmg,
                        const float* __restrict__ Wtg, const float* __restrict__ btg) {
    __shared__ float gs[HH];
    int b = blockIdx.x, t = threadIdx.x;   // 128 threads
    gs[t] = graph_fts[b*HH + t];
    __syncthreads();
    float ac0 = 0.f, ac1 = 0.f, ac2 = 0.f, ac3 = 0.f;
    #pragma unroll
    for (int k = 0; k < HH; k += 4) {
        ac0 += gs[k+0] * Wmg[(k+0)*DD + t];
        ac1 += gs[k+1] * Wmg[(k+1)*DD + t];
        ac2 += gs[k+2] * Wmg[(k+2)*DD + t];
        ac3 += gs[k+3] * Wmg[(k+3)*DD + t];
    }
    g_gm[b*DD + t] = bmg[t] + (ac0 + ac1) + (ac2 + ac3);
    if (t < TT) {
        float b0 = 0.f, b1 = 0.f, b2 = 0.f, b3 = 0.f;
        #pragma unroll
        for (int k = 0; k < HH; k += 4) {
            b0 += gs[k+0] * Wtg[(k+0)*TT + t];
            b1 += gs[k+1] * Wtg[(k+1)*TT + t];
            b2 += gs[k+2] * Wtg[(k+2)*TT + t];
            b3 += gs[k+3] * Wtg[(k+3)*TT + t];
        }
        g_tg[b*TT + t] = btg[t] + (b0 + b1) + (b2 + b3);
    }
}

// -------- per-node precompute: 8 rows/block, weights staged via cp.async --------
__global__ void __launch_bounds__(256)
k_node(const float* __restrict__ node, const float* __restrict__ hidden,
       const float* __restrict__ Wm1, const float* __restrict__ bm1,
       const float* __restrict__ Wm2, const float* __restrict__ bm2,
       const float* __restrict__ bme,
       const float* __restrict__ Wo1, const float* __restrict__ bo1,
       const float* __restrict__ Wt1, const float* __restrict__ bt1,
       const float* __restrict__ Wt2, const float* __restrict__ bt2,
       const float* __restrict__ bte) {
    extern __shared__ float ns[];
    float* swt = ns + NODE_WT_OFF;     // Wt1[2048], Wt2[2048]
    float* zs  = ns + NODE_ZS_OFF;     // [8][256]
    const uint32_t smb = smem_u32(ns);
    const int row0 = blockIdx.x * 8;
    const int b    = row0 / NN;
    const int tid  = threadIdx.x;      // 256
    const int half = tid >> 7;         // rows r0..r0+3
    const int t    = tid & 127;
    const int r0   = half * 4;

    // prefetch Wt1/Wt2 (1024 f4) + weight tile 0 (3072 f4) as group 0
    #pragma unroll
    for (int u = 0; u < 4; u++) {
        int f = u*256 + tid;
        const float* src = (f < 512) ? (Wt1 + f*4) : (Wt2 + (f - 512)*4);
        CP_ASYNC16(smb + (NODE_WT_OFF + f*4)*4, src);
    }
    #pragma unroll
    for (int u = 0; u < 12; u++) {
        int f = u*256 + tid;
        int w = f >> 10, g = f & 1023;
        int k = (g >> 5), c4 = g & 31;
        const float* W = (w == 0) ? Wm1 : ((w == 1) ? Wm2 : Wo1);
        CP_ASYNC16(smb + (w*4096 + g*4)*4, W + k*DD + c4*4);
    }
    CP_COMMIT();

    // load z into smem
    for (int x = tid; x < 8*ZZ; x += 256) {
        int r = x >> 8, k = x & 255;
        zs[x] = (k < HH) ? node[(row0 + r)*HH + k]
                         : hidden[(row0 + r)*HH + (k - HH)];
    }

    float a1[4], a2[4], a3[4];
    const float bia = bm1[t] + bm2[t] + bme[t] + g_gm[b*DD + t];
    const float bio = bo1[t];
    #pragma unroll
    for (int rr = 0; rr < 4; rr++) { a1[rr] = bia; a2[rr] = 0.f; a3[rr] = bio; }

    for (int kt = 0; kt < ZZ/KT; kt++) {
        const int p = kt & 1;
        if (kt + 1 < ZZ/KT) {   // prefetch next tile into other buffer
            const int pn = 1 - p;
            #pragma unroll
            for (int u = 0; u < 12; u++) {
                int f = u*256 + tid;
                int w = f >> 10, g = f & 1023;
                int k = (kt+1)*KT + (g >> 5), c4 = g & 31;
                const float* W = (w == 0) ? Wm1 : ((w == 1) ? Wm2 : Wo1);
                CP_ASYNC16(smb + (pn*12288 + w*4096 + g*4)*4, W + k*DD + c4*4);
            }
            CP_COMMIT();
            CP_WAIT1();
        } else {
            CP_WAIT0();
        }
        __syncthreads();
        const float* w1 = ns + p*12288;
        const float* w2 = w1 + 4096;
        const float* w3 = w1 + 8192;
        #pragma unroll 4
        for (int kk = 0; kk < KT; kk++) {
            const int k = kt*KT + kk;
            float v1 = w1[kk*128 + t], v2 = w2[kk*128 + t], v3 = w3[kk*128 + t];
            #pragma unroll
            for (int rr = 0; rr < 4; rr++) {
                float zk = zs[(r0 + rr)*ZZ + k];
                a1[rr] += zk*v1; a2[rr] += zk*v2; a3[rr] += zk*v3;
            }
        }
        __syncthreads();   // compute done before next overwrite of buffer p
    }
    #pragma unroll
    for (int rr = 0; rr < 4; rr++) {
        g_M1c[(row0 + r0 + rr)*DD + t] = a1[rr];
        g_M2 [(row0 + r0 + rr)*DD + t] = a2[rr];
        g_o1 [(row0 + r0 + rr)*DD + t] = a3[rr];
    }

    // triplet heads from smem: tid<128 -> (r = tid>>4, which = (tid>>3)&1, tt = tid&7)
    if (tid < 128) {
        int r = tid >> 4, which = (tid >> 3) & 1, tt = tid & 7;
        const float* W = swt + which*2048;
        float c0 = 0.f, c1 = 0.f, c2 = 0.f, c3 = 0.f;
        #pragma unroll 2
        for (int k = 0; k < ZZ; k += 4) {
            c0 += zs[r*ZZ + k+0] * W[(k+0)*TT + tt];
            c1 += zs[r*ZZ + k+1] * W[(k+1)*TT + tt];
            c2 += zs[r*ZZ + k+2] * W[(k+2)*TT + tt];
            c3 += zs[r*ZZ + k+3] * W[(k+3)*TT + tt];
        }
        float a = (c0 + c1) + (c2 + c3);
        if (which) g_T2 [(row0 + r)*TT + tt] = a;
        else       g_T1c[(row0 + r)*TT + tt] = bt1[tt] + bt2[tt] + bte[tt] + g_tg[b*TT + tt] + a;
    }
}

// -------- fused edge GEMM: MMA overlapped with next-chunk convert --------
__global__ void __launch_bounds__(NTH, 1)
k_main(const float* __restrict__ edge, const float* __restrict__ adj,
       const float* __restrict__ Wme, const float* __restrict__ Wte,
       float* __restrict__ tri_out) {
    extern __shared__ char sm[];
    const uint32_t smb = smem_u32(sm);
    const int tid  = threadIdx.x;
    const int lane = tid & 31, wid = tid >> 5;
    const int qr   = lane >> 2, qc = lane & 3;
    const int wm   = wid >> 2, wn = wid & 3;     // 2m x 4n warp grid, m64 x n32 per warp
    const int jb   = blockIdx.x, ig = blockIdx.y, b = blockIdx.z;
    const int j0   = jb * TJ;
    const int i0   = ig * ISPAN;
    const size_t ebase = ((size_t)b*NN)*NN*HH;

    // ---- convert B = Wme -> [n][k] bf16 hi/lo
    for (int idx = tid; idx < HH*DD; idx += NTH) {
        int k = idx >> 7, n = idx & 127;
        float w = Wme[idx];
        unsigned bw = __float_as_uint(w) & 0xFFFF0000u;
        *(unsigned short*)(sm + OFF_BH + n*BROW + k*2) = (unsigned short)(bw >> 16);
        *(__nv_bfloat16*)(sm + OFF_BL + n*BROW + k*2) = __float2bfloat16(w - __uint_as_float(bw));
    }
    for (int idx = tid; idx < HH*TT; idx += NTH) {
        int k = idx >> 3, n = idx & 7;
        float w = Wte[idx];
        unsigned bw = __float_as_uint(w) & 0xFFFF0000u;
        *(unsigned short*)(sm + OFF_BTH + n*BROW + k*2) = (unsigned short)(bw >> 16);
        *(__nv_bfloat16*)(sm + OFF_BTL + n*BROW + k*2) = __float2bfloat16(w - __uint_as_float(bw));
    }

    // ---- prologue: convert chunk 0 into buffer 0 (exposed once)
    {
        #pragma unroll
        for (int s = 0; s < 16; s++) {
            int F4 = s*NTH + tid;
            int e = F4 >> 5, k = (F4 & 31) << 2;
            int di = e >> 4, dj = e & 15;
            float4 v = *(const float4*)(edge + ebase + ((size_t)(i0 + di)*NN + (j0 + dj))*(size_t)HH + k);
            unsigned h01, l01, h23, l23;
            cvt_hilo(v.x, v.y, h01, l01);
            cvt_hilo(v.z, v.w, h23, l23);
            *(uint2*)(sm + OFF_A + e*BROW + k*2)         = make_uint2(h01, h23);
            *(uint2*)(sm + OFF_A + 34816 + e*BROW + k*2) = make_uint2(l01, l23);
        }
    }

    // fragment lane offsets
    const uint32_t aoff  = (uint32_t)((wm*64 + (lane & 15))*BROW + (((lane >> 4) << 3)) * 2);
    const uint32_t boff  = (uint32_t)((wn*32 + ((lane >> 4) << 3) + (lane & 7))*BROW + ((((lane >> 3) & 1) << 3)) * 2);
    const uint32_t btoff = (uint32_t)((lane & 7)*BROW + ((((lane >> 3) & 1) << 3)) * 2);
    const uint32_t bHb = smb + OFF_BH + boff,  bLb = smb + OFF_BL + boff;
    const uint32_t tHb = smb + OFF_BTH + btoff, tLb = smb + OFF_BTL + btoff;

    // hoisted T1 (receiver-side, chunk-invariant)
    const int ja = j0 + qr, jb2 = j0 + qr + 8;
    const float2 t1a = *(const float2*)(&g_T1c[((size_t)b*NN + ja )*TT + 2*qc]);
    const float2 t1b = *(const float2*)(&g_T1c[((size_t)b*NN + jb2)*TT + 2*qc]);

    float rmax[4][4];
    #pragma unroll
    for (int nt = 0; nt < 4; nt++)
        #pragma unroll
        for (int q = 0; q < 4; q++) rmax[nt][q] = -CUDART_INF_F;
    bool sawz0 = false, sawz1 = false;

    __syncthreads();   // buffer 0 ready

    for (int ci = 0; ci < NCHUNK; ci++) {
        const int i0c = i0 + ci*CI;
        const int p = ci & 1;
        const bool conv = (ci + 1 < NCHUNK);
        const int i0n = i0c + CI;
        const uint32_t aHb = smb + OFF_A + p*69632 + aoff;
        const uint32_t aLb = aHb + 34816;
        char* dstH = sm + OFF_A + (1-p)*69632;
        char* dstL = dstH + 34816;

        // prefetch adjacency for this chunk's epilogue
        float a0v[4], a1v[4];
        #pragma unroll
        for (int mt = 0; mt < 4; mt++) {
            const int i = i0c + wm*4 + mt;
            a0v[mt] = adj[((size_t)b*NN + i)*NN + j0 + qr];
            a1v[mt] = adj[((size_t)b*NN + i)*NN + j0 + qr + 8];
        }

        // register pipeline for next-chunk loads (2 float4 per ks)
        float4 v[2][2];
        if (conv) {
            #pragma unroll
            for (int u = 0; u < 2; u++) {
                int F4 = u*NTH + tid;
                int e = F4 >> 5, k = (F4 & 31) << 2;
                v[0][u] = *(const float4*)(edge + ebase + ((size_t)(i0n + (e>>4))*NN + (j0 + (e&15)))*(size_t)HH + k);
            }
        }

        float c[4][4][4];
        float ct[4] = {0.f, 0.f, 0.f, 0.f};
        #pragma unroll
        for (int mt = 0; mt < 4; mt++)
            #pragma unroll
            for (int nt = 0; nt < 4; nt++)
                #pragma unroll
                for (int q = 0; q < 4; q++) c[mt][nt][q] = 0.f;

        #pragma unroll
        for (int ks = 0; ks < 8; ks++) {
            if (conv && ks < 7) {
                #pragma unroll
                for (int u = 0; u < 2; u++) {
                    int F4 = (2*ks + 2 + u)*NTH + tid;
                    int e = F4 >> 5, k = (F4 & 31) << 2;
                    v[(ks+1)&1][u] = *(const float4*)(edge + ebase + ((size_t)(i0n + (e>>4))*NN + (j0 + (e&15)))*(size_t)HH + k);
                }
            }
            const uint32_t kb = ks * 32;
            uint32_t bH[2][4], bL[2][4];
            LDMX4(bH[0][0], bH[0][1], bH[0][2], bH[0][3], bHb + kb);
            LDMX4(bH[1][0], bH[1][1], bH[1][2], bH[1][3], bHb + 16*BROW + kb);
            LDMX4(bL[0][0], bL[0][1], bL[0][2], bL[0][3], bLb + kb);
            LDMX4(bL[1][0], bL[1][1], bL[1][2], bL[1][3], bLb + 16*BROW + kb);
            uint32_t t0h, t1h, t0l, t1l;
            LDMX2(t0h, t1h, tHb + kb);
            LDMX2(t0l, t1l, tLb + kb);
            #pragma unroll
            for (int mt = 0; mt < 4; mt++) {
                uint32_t aH[4], aL[4];
                LDMX4(aH[0], aH[1], aH[2], aH[3], aHb + mt*16*BROW + kb);
                LDMX4(aL[0], aL[1], aL[2], aL[3], aLb + mt*16*BROW + kb);
                #pragma unroll
                for (int nt = 0; nt < 4; nt++) {
                    uint32_t b0h = bH[nt>>1][(nt&1)*2], b1h = bH[nt>>1][(nt&1)*2+1];
                    uint32_t b0l = bL[nt>>1][(nt&1)*2], b1l = bL[nt>>1][(nt&1)*2+1];
                    mma16816(c[mt][nt], aH, b0h, b1h);
                    mma16816(c[mt][nt], aH, b0l, b1l);
                    mma16816(c[mt][nt], aL, b0h, b1h);
                }
                if (mt == wn) {
                    mma16816(ct, aH, t0h, t1h);
                    mma16816(ct, aH, t0l, t1l);
                    mma16816(ct, aL, t0h, t1h);
                }
            }
            if (conv) {
                #pragma unroll
                for (int u = 0; u < 2; u++) {
                    int F4 = (2*ks + u)*NTH + tid;
                    int e = F4 >> 5, k = (F4 & 31) << 2;
                    unsigned h01, l01, h23, l23;
                    cvt_hilo(v[ks&1][u].x, v[ks&1][u].y, h01, l01);
                    cvt_hilo(v[ks&1][u].z, v[ks&1][u].w, h23, l23);
                    *(uint2*)(dstH + e*BROW + k*2) = make_uint2(h01, h23);
                    *(uint2*)(dstL + e*BROW + k*2) = make_uint2(l01, l23);
                }
            }
        }

        // ---- register epilogue: tri write (sender i = i0c + wm*4 + wn)
        {
            const int i  = i0c + wm*4 + wn;
            const float2 t2v = *(const float2*)(&g_T2[((size_t)b*NN + i)*TT + 2*qc]);
            float2 oa, ob;
            oa.x = fmaxf(ct[0] + t1a.x + t2v.x, 0.f);
            oa.y = fmaxf(ct[1] + t1a.y + t2v.y, 0.f);
            ob.x = fmaxf(ct[2] + t1b.x + t2v.x, 0.f);
            ob.y = fmaxf(ct[3] + t1b.y + t2v.y, 0.f);
            *(float2*)(tri_out + (((size_t)b*NN + i)*NN + ja )*(size_t)TT + 2*qc) = oa;
            *(float2*)(tri_out + (((size_t)b*NN + i)*NN + jb2)*(size_t)TT + 2*qc) = ob;
        }
        // ---- register epilogue: masked max
        #pragma unroll
        for (int mt = 0; mt < 4; mt++) {
            const int i = i0c + wm*4 + mt;
            float2 m2v[4];
            #pragma unroll
            for (int nt = 0; nt < 4; nt++)
                m2v[nt] = *(const float2*)(&g_M2[((size_t)b*NN + i)*DD + wn*32 + nt*8 + 2*qc]);
            if (a0v[mt] != 0.0f) {
                #pragma unroll
                for (int nt = 0; nt < 4; nt++) {
                    rmax[nt][0] = fmaxf(rmax[nt][0], c[mt][nt][0] + m2v[nt].x);
                    rmax[nt][1] = fmaxf(rmax[nt][1], c[mt][nt][1] + m2v[nt].y);
                }
            } else sawz0 = true;
            if (a1v[mt] != 0.0f) {
                #pragma unroll
                for (int nt = 0; nt < 4; nt++) {
                    rmax[nt][2] = fmaxf(rmax[nt][2], c[mt][nt][2] + m2v[nt].x);
                    rmax[nt][3] = fmaxf(rmax[nt][3], c[mt][nt][3] + m2v[nt].y);
                }
            } else sawz1 = true;
        }

        __syncthreads();   // buffer 1-p fully written; buffer p reads done
    }

    // ---- cross-wm combine (2 groups) in now-dead A smem
    float* red  = (float*)(sm + OFF_A);            // [16][128]
    float* zbuf = (float*)(sm + OFF_A + 16*128*4); // [2][16]
    if (wn == 0 && qc == 0) {
        zbuf[wm*16 + qr]     = sawz0 ? 0.0f : -CUDART_INF_F;
        zbuf[wm*16 + qr + 8] = sawz1 ? 0.0f : -CUDART_INF_F;
    }
    if (wm == 1) {
        #pragma unroll
        for (int nt = 0; nt < 4; nt++) {
            #pragma unroll
            for (int q = 0; q < 4; q++) {
                int recv = qr + (q >> 1)*8;
                int col  = wn*32 + nt*8 + 2*qc + (q & 1);
                red[recv*128 + col] = rmax[nt][q];
            }
        }
    }
    __syncthreads();
    if (wm == 0) {
        #pragma unroll
        for (int q2 = 0; q2 < 2; q2++) {
            const int recv = qr + q2*8;
            const int j = j0 + recv;
            const float z = fmaxf(zbuf[recv], zbuf[16 + recv]);
            #pragma unroll
            for (int nt = 0; nt < 4; nt++) {
                const int col = wn*32 + nt*8 + 2*qc;
                float v0 = fmaxf(rmax[nt][q2*2 + 0], red[recv*128 + col]);
                float v1 = fmaxf(rmax[nt][q2*2 + 1], red[recv*128 + col + 1]);
                float2 m1 = *(const float2*)(&g_M1c[((size_t)b*NN + j)*DD + col]);
                float2 o;
                o.x = fmaxf(v0 + m1.x, z);
                o.y = fmaxf(v1 + m1.y, z);
                *(float2*)(&g_part[(((size_t)ig*BB + b)*NN + j)*DD + col]) = o;
            }
        }
    }
}

// -------- output head: Wo2 staged to smem via cp.async --------
__global__ void __launch_bounds__(128)
k_final(const float* __restrict__ Wo2, const float* __restrict__ bo2,
        float* __restrict__ ret) {
    extern __shared__ float fs[];       // Wo2[16384], ms[4][128]
    float* ms = fs + FIN_MS_OFF;
    const uint32_t smb = smem_u32(fs);
    const int row0 = blockIdx.x * 4;
    const int t = threadIdx.x;          // 128

    #pragma unroll
    for (int u = 0; u < 32; u++) {      // 4096 float4s / 128 threads
        int f = u*128 + t;
        CP_ASYNC16(smb + f*16, Wo2 + f*4);
    }
    CP_COMMIT();

    #pragma unroll
    for (int r = 0; r < 4; r++) {
        float v = -CUDART_INF_F;
        #pragma unroll
        for (int g = 0; g < IGRP; g++)
            v = fmaxf(v, g_part[(size_t)g*BB*NN*DD + (size_t)(row0 + r)*DD + t]);
        ms[r*DD + t] = v;
    }
    CP_WAIT0();
    __syncthreads();

    float acc[4];
    const float bia = bo2[t];
    #pragma unroll
    for (int r = 0; r < 4; r++) acc[r] = g_o1[(row0 + r)*DD + t] + bia;
    #pragma unroll 4
    for (int k = 0; k < DD; k++) {
        float w = fs[k*DD + t];
        #pragma unroll
        for (int r = 0; r < 4; r++) acc[r] += ms[r*DD + k] * w;
    }
    #pragma unroll
    for (int r = 0; r < 4; r++) ret[(row0 + r)*DD + t] = acc[r];
}

extern "C" void kernel_launch(void* const* d_in, const int* in_sizes, int n_in,
                              void* d_out, int out_size) {
    (void)in_sizes; (void)n_in; (void)out_size;
    const float* node   = (const float*)d_in[0];
    const float* edge   = (const float*)d_in[1];
    const float* graph  = (const float*)d_in[2];
    const float* adj    = (const float*)d_in[3];
    const float* hidden = (const float*)d_in[4];
    const float* Wm1 = (const float*)d_in[5],  *bm1 = (const float*)d_in[6];
    const float* Wm2 = (const float*)d_in[7],  *bm2 = (const float*)d_in[8];
    const float* Wme = (const float*)d_in[9],  *bme = (const float*)d_in[10];
    const float* Wmg = (const float*)d_in[11], *bmg = (const float*)d_in[12];
    const float* Wo1 = (const float*)d_in[13], *bo1 = (const float*)d_in[14];
    const float* Wo2 = (const float*)d_in[15], *bo2 = (const float*)d_in[16];
    const float* Wt1 = (const float*)d_in[17], *bt1 = (const float*)d_in[18];
    const float* Wt2 = (const float*)d_in[19], *bt2 = (const float*)d_in[20];
    const float* Wte = (const float*)d_in[21], *bte = (const float*)d_in[22];
    const float* Wtg = (const float*)d_in[23], *btg = (const float*)d_in[24];

    float* ret = (float*)d_out;
    float* tri = (float*)d_out + (size_t)BB*NN*DD;

    cudaFuncSetAttribute(k_main, cudaFuncAttributeMaxDynamicSharedMemorySize, SMEM_MAIN);
    cudaFuncSetAttribute(k_node, cudaFuncAttributeMaxDynamicSharedMemorySize, NODE_SMEM_B);
    cudaFuncSetAttribute(k_final, cudaFuncAttributeMaxDynamicSharedMemorySize, FIN_SMEM_B);

    k_graph<<<BB, 128>>>(graph, Wmg, bmg, Wtg, btg);
    k_node<<<BB*NN/8, 256, NODE_SMEM_B>>>(node, hidden,
                             Wm1, bm1, Wm2, bm2, bme,
                             Wo1, bo1, Wt1, bt1, Wt2, bt2, bte);
    k_main<<<dim3(NN/TJ, IGRP, BB), NTH, SMEM_MAIN>>>(edge, adj, Wme, Wte, tri);
    k_final<<<BB*NN/4, 128, FIN_SMEM_B>>>(Wo2, bo2, ret);
}